// round 7
// baseline (speedup 1.0000x reference)
#include <cuda_runtime.h>
#include <cstdint>

// ---------------- problem constants ----------------
#define NPOS   8000
#define CCH    128
#define CQ     16
#define NSPLIT 5
#define JT_PER 25        // 125 j-tiles / 5 splits
#define QT     125       // q tiles of 64

#define KPAD 20
#define VPAD 68          // V smem pitch ([c][j] layout)
#define PPAD 68

// smem float offsets
#define OFF_Q  0                    // [64][20]
#define OFF_K  1280                 // [2][64][20]
#define OFF_V  3840                 // [2][128][68]
#define OFF_P  21248                // [64][68]
#define OFF_L  25600                // [64]
#define SM_FLOATS 25664
#define FLASH_SMEM (SM_FLOATS * 4)  // 102656 B

// ---------------- device scratch ----------------
__device__ float g_q[NPOS * CQ];            // [n][d], tf32-rounded
__device__ float g_k[NPOS * CQ];            // [n][d], tf32-rounded
__device__ float g_v[(size_t)CCH * NPOS];   // [c][n], tf32-rounded
__device__ float g_waT[CCH * CCH];
__device__ float g_pacc[(size_t)NSPLIT * NPOS * CCH];
__device__ float g_pl[NSPLIT * NPOS];
__device__ float g_av[(size_t)NPOS * CCH];  // [n][c]
__device__ float g_y[(size_t)CCH * NPOS];
__device__ float g_mean[CCH], g_rstd[CCH];

// ---------------- helpers ----------------
__device__ __forceinline__ uint32_t smem_u32(const void* p) {
    uint32_t a;
    asm("{ .reg .u64 t; cvta.to.shared.u64 t, %1; cvt.u32.u64 %0, t; }" : "=r"(a) : "l"(p));
    return a;
}
__device__ __forceinline__ float rna_tf32(float x) {
    uint32_t t; asm("cvt.rna.tf32.f32 %0, %1;" : "=r"(t) : "f"(x));
    return __uint_as_float(t);
}
__device__ __forceinline__ uint32_t tf32_bits(float x) {
    uint32_t t; asm("cvt.rna.tf32.f32 %0, %1;" : "=r"(t) : "f"(x));
    return t;
}
__device__ __forceinline__ void mma_tf32(float d[4],
                                         uint32_t a0, uint32_t a1, uint32_t a2, uint32_t a3,
                                         uint32_t b0, uint32_t b1) {
    asm volatile("mma.sync.aligned.m16n8k8.row.col.f32.tf32.tf32.f32 "
                 "{%0,%1,%2,%3}, {%4,%5,%6,%7}, {%8,%9}, {%0,%1,%2,%3};"
                 : "+f"(d[0]), "+f"(d[1]), "+f"(d[2]), "+f"(d[3])
                 : "r"(a0), "r"(a1), "r"(a2), "r"(a3), "r"(b0), "r"(b1));
}
__device__ __forceinline__ void ldsm4(uint32_t r[4], uint32_t addr) {
    asm volatile("ldmatrix.sync.aligned.m8n8.x4.shared.b16 {%0,%1,%2,%3}, [%4];"
                 : "=r"(r[0]), "=r"(r[1]), "=r"(r[2]), "=r"(r[3]) : "r"(addr));
}
#define CPA16(dst, src) \
    asm volatile("cp.async.cg.shared.global [%0], [%1], 16;" :: "r"(dst), "l"(src))
#define CP_COMMIT() asm volatile("cp.async.commit_group;" ::: "memory")
#define CP_WAIT0()  asm volatile("cp.async.wait_group 0;" ::: "memory")

// ---------------- kernel: transpose wa ----------------
__global__ void k_transpose_w(const float* __restrict__ wa) {
    int i = blockIdx.x * blockDim.x + threadIdx.x;   // 16384
    int r = i >> 7, c = i & 127;
    g_waT[c * CCH + r] = wa[r * CCH + c];
}

// ---------------- kernel: q/k projections, x read once ----------------
__global__ void __launch_bounds__(256) k_proj_qk(const float* __restrict__ x,
                                                 const float* __restrict__ wq,
                                                 const float* __restrict__ bq,
                                                 const float* __restrict__ wk,
                                                 const float* __restrict__ bk) {
    __shared__ float swT[CCH * 32];   // [cc][32 outputs: 16 q | 16 k]
    __shared__ float sb[32];
    const int tid = threadIdx.x;
    for (int i = tid; i < 16 * CCH; i += 256) {
        int d = i >> 7, cc = i & 127;
        swT[cc * 32 + d]      = wq[i];
        swT[cc * 32 + 16 + d] = wk[i];
    }
    if (tid < 16) sb[tid] = bq[tid];
    else if (tid < 32) sb[tid] = bk[tid - 16];
    __syncthreads();

    const int n = blockIdx.x * 256 + tid;
    if (n >= NPOS) return;
    float acc[32];
    #pragma unroll
    for (int i = 0; i < 32; i++) acc[i] = sb[i];
    #pragma unroll 2
    for (int cc = 0; cc < CCH; cc++) {
        float xv = x[cc * NPOS + n];
        const float4* wr = (const float4*)&swT[cc * 32];
        #pragma unroll
        for (int i8 = 0; i8 < 8; i8++) {
            float4 w = wr[i8];
            acc[i8 * 4 + 0] += w.x * xv;
            acc[i8 * 4 + 1] += w.y * xv;
            acc[i8 * 4 + 2] += w.z * xv;
            acc[i8 * 4 + 3] += w.w * xv;
        }
    }
    #pragma unroll
    for (int d = 0; d < CQ; d++) g_q[n * CQ + d] = rna_tf32(acc[d]);
    #pragma unroll
    for (int d = 0; d < CQ; d++) g_k[n * CQ + d] = rna_tf32(acc[16 + d]);
}

// ---------------- kernel: v projection -> [c][n], x read 4x ----------------
__global__ void __launch_bounds__(256) k_proj_v(const float* __restrict__ x,
                                                const float* __restrict__ wv,
                                                const float* __restrict__ bv) {
    __shared__ float swT[CCH * 32];   // [cc][32 c-outputs]
    const int tid = threadIdx.x;
    const int cb = blockIdx.y * 32;
    for (int i = tid; i < 32 * CCH; i += 256) {
        int r = i >> 7, cc = i & 127;
        swT[cc * 32 + r] = wv[(cb + r) * CCH + cc];
    }
    __syncthreads();

    const int n = blockIdx.x * 256 + tid;
    if (n >= NPOS) return;
    float acc[32];
    #pragma unroll
    for (int i = 0; i < 32; i++) acc[i] = bv[cb + i];
    #pragma unroll 2
    for (int cc = 0; cc < CCH; cc++) {
        float xv = x[cc * NPOS + n];
        const float4* wr = (const float4*)&swT[cc * 32];
        #pragma unroll
        for (int i8 = 0; i8 < 8; i8++) {
            float4 w = wr[i8];
            acc[i8 * 4 + 0] += w.x * xv;
            acc[i8 * 4 + 1] += w.y * xv;
            acc[i8 * 4 + 2] += w.z * xv;
            acc[i8 * 4 + 3] += w.w * xv;
        }
    }
    #pragma unroll
    for (int i = 0; i < 32; i++)
        g_v[(size_t)(cb + i) * NPOS + n] = rna_tf32(acc[i]);
}

// ---------------- kernel: flash attention, mma.sync tf32 + ldmatrix ----------------
__global__ void __launch_bounds__(256, 2) k_flash_mma() {
    extern __shared__ float sm[];
    float* sQ = sm + OFF_Q;
    float* sP = sm + OFF_P;
    float* sL = sm + OFF_L;
    const uint32_t smb = smem_u32(sm);

    const int tid  = threadIdx.x;
    const int wid  = tid >> 5;
    const int lane = tid & 31;
    const int g    = lane >> 2;     // groupID (0..7)
    const int tq   = lane & 3;      // threadID_in_group

    const int qt = blockIdx.x, sp = blockIdx.y;
    const int qbase = qt * 64;
    const int jt0 = sp * JT_PER;

    // MMA1/softmax mapping: 4 q-blocks x 2 j-halves
    const int qb = (wid >> 1) * 16;
    const int jh = (wid & 1) * 32;
    // MMA2 mapping: 2 q-halves x 4 c-quarters
    const int qh2 = (wid >> 2) * 32;
    const int cq  = (wid & 3) * 32;

    if (tid < 64) sL[tid] = 0.f;

    // load Q tile: 64 rows x 16 floats
    {
        int j = tid >> 2, seg = tid & 3;
        *(float4*)&sQ[j * KPAD + seg * 4] =
            *(const float4*)&g_q[(qbase + j) * CQ + seg * 4];
    }

    auto prefetch = [&](int jt, int bufi) {
        const int jb = jt * 64;
        {   // K: 64 rows x 16 floats
            int j = tid >> 2, seg = tid & 3;
            uint32_t dst = smb + (OFF_K + bufi * 1280 + j * KPAD + seg * 4) * 4;
            CPA16(dst, &g_k[(jb + j) * CQ + seg * 4]);
        }
        #pragma unroll
        for (int i = 0; i < 8; i++) {   // V: [128 c][64 j]
            int idx = tid + i * 256;          // 0..2047
            int c = idx >> 4, j4 = idx & 15;
            uint32_t dst = smb + (OFF_V + bufi * 8704 + c * VPAD + j4 * 4) * 4;
            CPA16(dst, &g_v[(size_t)c * NPOS + jb + j4 * 4]);
        }
        CP_COMMIT();
    };

    float D[2][4][4];
    #pragma unroll
    for (int qi = 0; qi < 2; qi++)
        #pragma unroll
        for (int nt = 0; nt < 4; nt++)
            #pragma unroll
            for (int k = 0; k < 4; k++) D[qi][nt][k] = 0.f;
    float l0 = 0.f, l1 = 0.f;

    int buf = 0;
    prefetch(jt0, 0);
    __syncthreads();   // sQ visible before hoisted ldmatrix

    // hoisted Q A-fragments (loop-invariant)
    uint32_t qa[2][4];
    {
        uint32_t base = smb + (OFF_Q + (qb + (lane & 15)) * KPAD + (lane >> 4) * 4) * 4;
        ldsm4(qa[0], base);
        ldsm4(qa[1], base + 8 * 4);
    }

    // per-thread ldmatrix address offsets
    const int arow1 = (lane & 15);             // A chunk row within 16
    const int acol  = (lane >> 4) * 4;         // A chunk col
    const int brow  = (lane & 7) + (lane >> 4) * 8;   // B chunk row within 16
    const int bcol  = (lane & 8) ? 4 : 0;             // B chunk col

    for (int it = 0; it < JT_PER; it++) {
        CP_WAIT0();
        __syncthreads();   // sync1: K/V(buf) visible to all warps;
                           // also: all warps finished MMA2(it-1) -> safe to
                           // overwrite V(buf^1) below and P in softmax.
        if (it + 1 < JT_PER) prefetch(jt0 + it + 1, buf ^ 1);

        // ---- MMA1: S[16q x 32j] per warp ----
        float S[4][4];
        #pragma unroll
        for (int nt = 0; nt < 4; nt++)
            #pragma unroll
            for (int k = 0; k < 4; k++) S[nt][k] = 0.f;

        {
            const uint32_t kbase = smb + (OFF_K + buf * 1280) * 4;
            #pragma unroll
            for (int kc = 0; kc < 2; kc++) {
                uint32_t kb0[4], kb1[4];
                ldsm4(kb0, kbase + ((jh + brow) * KPAD + kc * 8 + bcol) * 4);
                ldsm4(kb1, kbase + ((jh + 16 + brow) * KPAD + kc * 8 + bcol) * 4);
                mma_tf32(S[0], qa[kc][0], qa[kc][1], qa[kc][2], qa[kc][3], kb0[0], kb0[1]);
                mma_tf32(S[1], qa[kc][0], qa[kc][1], qa[kc][2], qa[kc][3], kb0[2], kb0[3]);
                mma_tf32(S[2], qa[kc][0], qa[kc][1], qa[kc][2], qa[kc][3], kb1[0], kb1[1]);
                mma_tf32(S[3], qa[kc][0], qa[kc][1], qa[kc][2], qa[kc][3], kb1[2], kb1[3]);
            }
        }

        // ---- softmax (no max-subtraction) + tf32 convert + store P ----
        #pragma unroll
        for (int nt = 0; nt < 4; nt++) {
            float p0 = __expf(S[nt][0]);
            float p1 = __expf(S[nt][1]);
            float p2 = __expf(S[nt][2]);
            float p3 = __expf(S[nt][3]);
            l0 += p0 + p1;
            l1 += p2 + p3;
            int col = jh + nt * 8 + 2 * tq;
            *(float2*)&sP[(qb + g) * PPAD + col] =
                make_float2(__uint_as_float(tf32_bits(p0)), __uint_as_float(tf32_bits(p1)));
            *(float2*)&sP[(qb + g + 8) * PPAD + col] =
                make_float2(__uint_as_float(tf32_bits(p2)), __uint_as_float(tf32_bits(p3)));
        }
        __syncthreads();   // sync2: P visible across warps

        // ---- MMA2: D[32q x 32c] per warp ----
        {
            const uint32_t pbase = smb + OFF_P * 4;
            const uint32_t vbase = smb + (OFF_V + buf * 8704) * 4;
            #pragma unroll
            for (int kc = 0; kc < 8; kc++) {
                uint32_t pa0[4], pa1[4], vb0[4], vb1[4];
                ldsm4(pa0, pbase + ((qh2 + arow1) * PPAD + kc * 8 + acol) * 4);
                ldsm4(pa1, pbase + ((qh2 + 16 + arow1) * PPAD + kc * 8 + acol) * 4);
                ldsm4(vb0, vbase + ((cq + brow) * VPAD + kc * 8 + bcol) * 4);
                ldsm4(vb1, vbase + ((cq + 16 + brow) * VPAD + kc * 8 + bcol) * 4);
                mma_tf32(D[0][0], pa0[0], pa0[1], pa0[2], pa0[3], vb0[0], vb0[1]);
                mma_tf32(D[0][1], pa0[0], pa0[1], pa0[2], pa0[3], vb0[2], vb0[3]);
                mma_tf32(D[0][2], pa0[0], pa0[1], pa0[2], pa0[3], vb1[0], vb1[1]);
                mma_tf32(D[0][3], pa0[0], pa0[1], pa0[2], pa0[3], vb1[2], vb1[3]);
                mma_tf32(D[1][0], pa1[0], pa1[1], pa1[2], pa1[3], vb0[0], vb0[1]);
                mma_tf32(D[1][1], pa1[0], pa1[1], pa1[2], pa1[3], vb0[2], vb0[3]);
                mma_tf32(D[1][2], pa1[0], pa1[1], pa1[2], pa1[3], vb1[0], vb1[1]);
                mma_tf32(D[1][3], pa1[0], pa1[1], pa1[2], pa1[3], vb1[2], vb1[3]);
            }
        }
        buf ^= 1;
        // no end-of-loop barrier: next iteration's sync1 orders everything.
    }

    // ---- l reduction ----
    l0 += __shfl_xor_sync(0xffffffffu, l0, 1);
    l0 += __shfl_xor_sync(0xffffffffu, l0, 2);
    l1 += __shfl_xor_sync(0xffffffffu, l1, 1);
    l1 += __shfl_xor_sync(0xffffffffu, l1, 2);
    if (tq == 0) {
        atomicAdd(&sL[qb + g], l0);
        atomicAdd(&sL[qb + g + 8], l1);
    }
    __syncthreads();
    if (tid < 64)
        g_pl[sp * NPOS + qbase + tid] = sL[tid];

    // ---- write D partials ----
    #pragma unroll
    for (int qi = 0; qi < 2; qi++) {
        #pragma unroll
        for (int nt = 0; nt < 4; nt++) {
            int col = cq + nt * 8 + 2 * tq;
            int r0 = qbase + qh2 + qi * 16 + g;
            *(float2*)&g_pacc[((size_t)sp * NPOS + r0) * CCH + col] =
                make_float2(D[qi][nt][0], D[qi][nt][1]);
            *(float2*)&g_pacc[((size_t)sp * NPOS + r0 + 8) * CCH + col] =
                make_float2(D[qi][nt][2], D[qi][nt][3]);
        }
    }
}

// ---------------- kernel: combine splits (pure addition) ----------------
__global__ void k_combine() {
    int q = blockIdx.x;
    int c = threadIdx.x;
    float L = 0.f;
    #pragma unroll
    for (int s = 0; s < NSPLIT; s++) L += g_pl[s * NPOS + q];
    float a = 0.f;
    #pragma unroll
    for (int s = 0; s < NSPLIT; s++) a += g_pacc[((size_t)s * NPOS + q) * CCH + c];
    g_av[(size_t)q * CCH + c] = a / L;
}

// ---------------- kernel: output projection y = wa @ av + ba ----------------
__global__ void __launch_bounds__(256) k_ygemm(const float* __restrict__ ba) {
    __shared__ float avs[64 * CCH];
    int tid = threadIdx.x;
    int nbase = blockIdx.x * 64;
    for (int t = tid; t < 64 * (CCH / 4); t += 256) {
        int n = t >> 5;
        int c4 = (t & 31) << 2;
        *(float4*)&avs[n * CCH + c4] = *(const float4*)&g_av[(size_t)(nbase + n) * CCH + c4];
    }
    __syncthreads();
    int c0 = (tid & 31) * 4;
    int n0 = (tid >> 5) * 8;
    float acc[8][4];
    #pragma unroll
    for (int i = 0; i < 8; i++)
        #pragma unroll
        for (int k = 0; k < 4; k++) acc[i][k] = 0.f;
    for (int cc = 0; cc < CCH; cc++) {
        float4 wf = *(const float4*)&g_waT[cc * CCH + c0];
        #pragma unroll
        for (int i = 0; i < 8; i++) {
            float a = avs[(n0 + i) * CCH + cc];
            acc[i][0] += a * wf.x;
            acc[i][1] += a * wf.y;
            acc[i][2] += a * wf.z;
            acc[i][3] += a * wf.w;
        }
    }
    #pragma unroll
    for (int k = 0; k < 4; k++) {
        float b = ba[c0 + k];
        #pragma unroll
        for (int i = 0; i < 8; i++)
            g_y[(size_t)(c0 + k) * NPOS + nbase + n0 + i] = acc[i][k] + b;
    }
}

// ---------------- kernel: per-channel BN stats ----------------
__global__ void k_stats() {
    int c = blockIdx.x;
    int tid = threadIdx.x;
    float s = 0.f, sq = 0.f;
    for (int n = tid; n < NPOS; n += 256) {
        float v = g_y[(size_t)c * NPOS + n];
        s += v; sq += v * v;
    }
    #pragma unroll
    for (int o = 16; o > 0; o >>= 1) {
        s  += __shfl_xor_sync(0xffffffffu, s, o);
        sq += __shfl_xor_sync(0xffffffffu, sq, o);
    }
    __shared__ float ws[8], wqs[8];
    int w = tid >> 5, l = tid & 31;
    if (l == 0) { ws[w] = s; wqs[w] = sq; }
    __syncthreads();
    if (tid == 0) {
        float ts = 0.f, tq2 = 0.f;
        #pragma unroll
        for (int i = 0; i < 8; i++) { ts += ws[i]; tq2 += wqs[i]; }
        float mean = ts / (float)NPOS;
        float var = tq2 / (float)NPOS - mean * mean;
        g_mean[c] = mean;
        g_rstd[c] = rsqrtf(var + 1e-5f);
    }
}

// ---------------- kernel: BN + ReLU + residual ----------------
__global__ void k_final(const float* __restrict__ x,
                        const float* __restrict__ bnw, const float* __restrict__ bnb,
                        float* __restrict__ out) {
    int idx = blockIdx.x * 256 + threadIdx.x;
    int c = idx / NPOS;
    float yv = g_y[idx];
    float o = (yv - g_mean[c]) * g_rstd[c] * bnw[c] + bnb[c];
    out[idx] = fmaxf(o, 0.f) + x[idx];
}

// ---------------- launch ----------------
extern "C" void kernel_launch(void* const* d_in, const int* in_sizes, int n_in,
                              void* d_out, int out_size) {
    const float* x   = (const float*)d_in[0];
    const float* wq  = (const float*)d_in[1];
    const float* bq  = (const float*)d_in[2];
    const float* wk  = (const float*)d_in[3];
    const float* bk  = (const float*)d_in[4];
    const float* wv  = (const float*)d_in[5];
    const float* bv  = (const float*)d_in[6];
    const float* wa  = (const float*)d_in[7];
    const float* ba  = (const float*)d_in[8];
    const float* bnw = (const float*)d_in[9];
    const float* bnb = (const float*)d_in[10];
    float* out = (float*)d_out;

    static int smem_set = 0;
    if (!smem_set) {
        cudaFuncSetAttribute(k_flash_mma, cudaFuncAttributeMaxDynamicSharedMemorySize,
                             FLASH_SMEM);
        smem_set = 1;
    }

    k_transpose_w<<<64, 256>>>(wa);
    k_proj_qk<<<32, 256>>>(x, wq, bq, wk, bk);
    k_proj_v<<<dim3(32, 4), 256>>>(x, wv, bv);
    k_flash_mma<<<dim3(QT, NSPLIT), 256, FLASH_SMEM>>>();
    k_combine<<<NPOS, CCH>>>();
    k_ygemm<<<NPOS / 64, 256>>>(ba);
    k_stats<<<CCH, 256>>>();
    k_final<<<(NPOS * CCH) / 256, 256>>>(x, bnw, bnb, out);
}

// round 8
// speedup vs baseline: 1.6391x; 1.6391x over previous
#include <cuda_runtime.h>
#include <cstdint>

// ---------------- problem constants ----------------
#define NPOS   8000
#define CCH    128
#define CQ     16
#define NSPLIT 5
#define JT_PER 25        // 125 j-tiles / 5 splits
#define QT     125       // q tiles of 64

#define KPAD 20
#define VPAD 68          // V smem pitch ([c][j] layout)
#define PPAD 68

// smem float offsets
#define OFF_Q  0                    // [64][20]
#define OFF_K  1280                 // [2][64][20]
#define OFF_V  3840                 // [2][128][68]
#define OFF_P  21248                // [64][68]
#define OFF_L  25600                // [64]
#define SM_FLOATS 25664
#define FLASH_SMEM (SM_FLOATS * 4)  // 102656 B

// ---------------- device scratch ----------------
__device__ float g_q[NPOS * CQ];            // [n][d], tf32-rounded
__device__ float g_k[NPOS * CQ];            // [n][d], tf32-rounded
__device__ float g_v[(size_t)CCH * NPOS];   // [c][n], tf32-rounded
__device__ float g_waT[CCH * CCH];
__device__ float g_pacc[(size_t)NSPLIT * NPOS * CCH];
__device__ float g_pl[NSPLIT * NPOS];
__device__ float g_av[(size_t)NPOS * CCH];  // [n][c]
__device__ float g_y[(size_t)CCH * NPOS];
__device__ float g_mean[CCH], g_rstd[CCH];

// ---------------- helpers ----------------
__device__ __forceinline__ uint32_t smem_u32(const void* p) {
    uint32_t a;
    asm("{ .reg .u64 t; cvta.to.shared.u64 t, %1; cvt.u32.u64 %0, t; }" : "=r"(a) : "l"(p));
    return a;
}
__device__ __forceinline__ float rna_tf32(float x) {
    uint32_t t; asm("cvt.rna.tf32.f32 %0, %1;" : "=r"(t) : "f"(x));
    return __uint_as_float(t);
}
__device__ __forceinline__ uint32_t tf32_bits(float x) {
    uint32_t t; asm("cvt.rna.tf32.f32 %0, %1;" : "=r"(t) : "f"(x));
    return t;
}
__device__ __forceinline__ void mma_tf32(float d[4],
                                         uint32_t a0, uint32_t a1, uint32_t a2, uint32_t a3,
                                         uint32_t b0, uint32_t b1) {
    asm volatile("mma.sync.aligned.m16n8k8.row.col.f32.tf32.tf32.f32 "
                 "{%0,%1,%2,%3}, {%4,%5,%6,%7}, {%8,%9}, {%0,%1,%2,%3};"
                 : "+f"(d[0]), "+f"(d[1]), "+f"(d[2]), "+f"(d[3])
                 : "r"(a0), "r"(a1), "r"(a2), "r"(a3), "r"(b0), "r"(b1));
}
__device__ __forceinline__ void ldsm4(uint32_t r[4], uint32_t addr) {
    asm volatile("ldmatrix.sync.aligned.m8n8.x4.shared.b16 {%0,%1,%2,%3}, [%4];"
                 : "=r"(r[0]), "=r"(r[1]), "=r"(r[2]), "=r"(r[3]) : "r"(addr));
}
#define CPA16(dst, src) \
    asm volatile("cp.async.cg.shared.global [%0], [%1], 16;" :: "r"(dst), "l"(src))
#define CP_COMMIT() asm volatile("cp.async.commit_group;" ::: "memory")
#define CP_WAIT1()  asm volatile("cp.async.wait_group 1;" ::: "memory")
#define CP_WAIT0()  asm volatile("cp.async.wait_group 0;" ::: "memory")

// ---------------- kernel: transpose wa ----------------
__global__ void k_transpose_w(const float* __restrict__ wa) {
    int i = blockIdx.x * blockDim.x + threadIdx.x;   // 16384
    int r = i >> 7, c = i & 127;
    g_waT[c * CCH + r] = wa[r * CCH + c];
}

// ---------------- kernel: q/k projections (smem weights, 4 outputs/thread) ----------------
__global__ void __launch_bounds__(256) k_proj_qk(const float* __restrict__ x,
                                                 const float* __restrict__ wq,
                                                 const float* __restrict__ bq,
                                                 const float* __restrict__ wk,
                                                 const float* __restrict__ bk) {
    __shared__ float swT[CCH * 32];   // [cc][32 outputs: 16 q | 16 k]
    __shared__ float sb[32];
    const int tid = threadIdx.x;
    for (int i = tid; i < 16 * CCH; i += 256) {
        int d = i >> 7, cc = i & 127;
        swT[cc * 32 + d]      = wq[i];
        swT[cc * 32 + 16 + d] = wk[i];
    }
    if (tid < 16) sb[tid] = bq[tid];
    else if (tid < 32) sb[tid] = bk[tid - 16];
    __syncthreads();

    const int n  = blockIdx.x * 32 + (tid & 31);   // 250 blocks x 32 n
    const int og = tid >> 5;                       // 0..7 -> outputs og*4..og*4+3
    float a0 = sb[og * 4 + 0], a1 = sb[og * 4 + 1];
    float a2 = sb[og * 4 + 2], a3 = sb[og * 4 + 3];
    #pragma unroll 4
    for (int cc = 0; cc < CCH; cc++) {
        float xv = x[cc * NPOS + n];
        float4 w = *(const float4*)&swT[cc * 32 + og * 4];
        a0 += w.x * xv; a1 += w.y * xv; a2 += w.z * xv; a3 += w.w * xv;
    }
    float* o = (og < 4) ? g_q : g_k;
    int d0 = (og < 4) ? og * 4 : (og - 4) * 4;
    o[n * CQ + d0 + 0] = rna_tf32(a0);
    o[n * CQ + d0 + 1] = rna_tf32(a1);
    o[n * CQ + d0 + 2] = rna_tf32(a2);
    o[n * CQ + d0 + 3] = rna_tf32(a3);
}

// ---------------- kernel: v projection -> [c][n], tf32-rounded, smem-tiled ----------------
__global__ void __launch_bounds__(256) k_proj_v(const float* __restrict__ x,
                                                const float* __restrict__ wv,
                                                const float* __restrict__ bv) {
    __shared__ float sw[32 * CCH];              // wv rows cb..cb+31
    const int tid = threadIdx.x;
    const int nb = blockIdx.x * 64;
    const int cb = blockIdx.y * 32;
    for (int i = tid; i < 32 * CCH; i += 256) {
        int r = i >> 7, c = i & 127;
        sw[i] = wv[(cb + r) * CCH + c];
    }
    __syncthreads();
    const int n = nb + (tid & 63);
    const int c0 = (tid >> 6) * 8;
    float acc[8];
    #pragma unroll
    for (int i = 0; i < 8; i++) acc[i] = bv[cb + c0 + i];
    #pragma unroll 4
    for (int cc4 = 0; cc4 < 32; cc4++) {
        float x0 = x[(cc4 * 4 + 0) * NPOS + n];
        float x1 = x[(cc4 * 4 + 1) * NPOS + n];
        float x2 = x[(cc4 * 4 + 2) * NPOS + n];
        float x3 = x[(cc4 * 4 + 3) * NPOS + n];
        #pragma unroll
        for (int i = 0; i < 8; i++) {
            float4 w = *(const float4*)&sw[(c0 + i) * CCH + cc4 * 4];
            acc[i] += w.x * x0 + w.y * x1 + w.z * x2 + w.w * x3;
        }
    }
    #pragma unroll
    for (int i = 0; i < 8; i++)
        g_v[(size_t)(cb + c0 + i) * NPOS + n] = rna_tf32(acc[i]);
}

// ---------------- kernel: flash attention, mma.sync tf32 + ldmatrix ----------------
__global__ void __launch_bounds__(256, 2) k_flash_mma() {
    extern __shared__ float sm[];
    float* sQ = sm + OFF_Q;
    float* sP = sm + OFF_P;
    float* sL = sm + OFF_L;
    const uint32_t smb = smem_u32(sm);

    const int tid  = threadIdx.x;
    const int wid  = tid >> 5;
    const int lane = tid & 31;
    const int g    = lane >> 2;     // groupID (0..7)
    const int tq   = lane & 3;      // threadID_in_group

    const int qt = blockIdx.x, sp = blockIdx.y;
    const int qbase = qt * 64;
    const int jt0 = sp * JT_PER;

    // MMA1/softmax mapping: 4 q-blocks x 2 j-halves
    const int qb = (wid >> 1) * 16;
    const int jh = (wid & 1) * 32;
    // MMA2 mapping: 2 q-halves x 4 c-quarters
    const int qh2 = (wid >> 2) * 32;
    const int cq  = (wid & 3) * 32;

    if (tid < 64) sL[tid] = 0.f;

    // load Q tile: 64 rows x 16 floats
    {
        int j = tid >> 2, seg = tid & 3;
        *(float4*)&sQ[j * KPAD + seg * 4] =
            *(const float4*)&g_q[(qbase + j) * CQ + seg * 4];
    }

    auto prefetch = [&](int jt, int bufi) {
        const int jb = jt * 64;
        {   // K: 64 rows x 16 floats
            int j = tid >> 2, seg = tid & 3;
            uint32_t dst = smb + (OFF_K + bufi * 1280 + j * KPAD + seg * 4) * 4;
            CPA16(dst, &g_k[(jb + j) * CQ + seg * 4]);
        }
        #pragma unroll
        for (int i = 0; i < 8; i++) {   // V: [128 c][64 j]
            int idx = tid + i * 256;          // 0..2047
            int c = idx >> 4, j4 = idx & 15;
            uint32_t dst = smb + (OFF_V + bufi * 8704 + c * VPAD + j4 * 4) * 4;
            CPA16(dst, &g_v[(size_t)c * NPOS + jb + j4 * 4]);
        }
        CP_COMMIT();
    };

    float D[2][4][4];
    #pragma unroll
    for (int qi = 0; qi < 2; qi++)
        #pragma unroll
        for (int nt = 0; nt < 4; nt++)
            #pragma unroll
            for (int k = 0; k < 4; k++) D[qi][nt][k] = 0.f;
    float l0 = 0.f, l1 = 0.f;

    int buf = 0;
    prefetch(jt0, 0);
    __syncthreads();   // sQ visible before hoisted ldmatrix

    // hoisted Q A-fragments (loop-invariant)
    uint32_t qa[2][4];
    {
        uint32_t base = smb + (OFF_Q + (qb + (lane & 15)) * KPAD + (lane >> 4) * 4) * 4;
        ldsm4(qa[0], base);
        ldsm4(qa[1], base + 8 * 4);
    }

    // per-thread ldmatrix address offsets
    const int arow1 = (lane & 15);             // A chunk row within 16
    const int acol  = (lane >> 4) * 4;         // A chunk col
    const int brow  = (lane & 7) + (lane >> 4) * 8;   // B chunk row within 16
    const int bcol  = (lane & 8) ? 4 : 0;             // B chunk col

    for (int it = 0; it < JT_PER; it++) {
        if (it + 1 < JT_PER) { prefetch(jt0 + it + 1, buf ^ 1); CP_WAIT1(); }
        else                 { CP_WAIT0(); }
        __syncthreads();   // sync1: K/V(buf) ready

        // ---- MMA1: S[16q x 32j] per warp ----
        float S[4][4];
        #pragma unroll
        for (int nt = 0; nt < 4; nt++)
            #pragma unroll
            for (int k = 0; k < 4; k++) S[nt][k] = 0.f;

        {
            const uint32_t kbase = smb + (OFF_K + buf * 1280) * 4;
            #pragma unroll
            for (int kc = 0; kc < 2; kc++) {
                uint32_t kb0[4], kb1[4];
                ldsm4(kb0, kbase + ((jh + brow) * KPAD + kc * 8 + bcol) * 4);
                ldsm4(kb1, kbase + ((jh + 16 + brow) * KPAD + kc * 8 + bcol) * 4);
                mma_tf32(S[0], qa[kc][0], qa[kc][1], qa[kc][2], qa[kc][3], kb0[0], kb0[1]);
                mma_tf32(S[1], qa[kc][0], qa[kc][1], qa[kc][2], qa[kc][3], kb0[2], kb0[3]);
                mma_tf32(S[2], qa[kc][0], qa[kc][1], qa[kc][2], qa[kc][3], kb1[0], kb1[1]);
                mma_tf32(S[3], qa[kc][0], qa[kc][1], qa[kc][2], qa[kc][3], kb1[2], kb1[3]);
            }
        }

        // ---- softmax (no max-subtraction) + tf32 convert + store P ----
        #pragma unroll
        for (int nt = 0; nt < 4; nt++) {
            float p0 = __expf(S[nt][0]);
            float p1 = __expf(S[nt][1]);
            float p2 = __expf(S[nt][2]);
            float p3 = __expf(S[nt][3]);
            l0 += p0 + p1;
            l1 += p2 + p3;
            int col = jh + nt * 8 + 2 * tq;
            *(float2*)&sP[(qb + g) * PPAD + col] =
                make_float2(__uint_as_float(tf32_bits(p0)), __uint_as_float(tf32_bits(p1)));
            *(float2*)&sP[(qb + g + 8) * PPAD + col] =
                make_float2(__uint_as_float(tf32_bits(p2)), __uint_as_float(tf32_bits(p3)));
        }
        // sync2 (split): MMA2 of warps 0-3 reads only P rows 0-31, written by
        // warps 0-3; warps 4-7 likewise for rows 32-63. V ordering came from
        // sync1. So a 128-thread named barrier per q-half suffices.
        if (wid < 4) asm volatile("bar.sync 3, 128;" ::: "memory");
        else         asm volatile("bar.sync 4, 128;" ::: "memory");

        // ---- MMA2: D[32q x 32c] per warp ----
        {
            const uint32_t pbase = smb + OFF_P * 4;
            const uint32_t vbase = smb + (OFF_V + buf * 8704) * 4;
            #pragma unroll
            for (int kc = 0; kc < 8; kc++) {
                uint32_t pa0[4], pa1[4], vb0[4], vb1[4];
                ldsm4(pa0, pbase + ((qh2 + arow1) * PPAD + kc * 8 + acol) * 4);
                ldsm4(pa1, pbase + ((qh2 + 16 + arow1) * PPAD + kc * 8 + acol) * 4);
                ldsm4(vb0, vbase + ((cq + brow) * VPAD + kc * 8 + bcol) * 4);
                ldsm4(vb1, vbase + ((cq + 16 + brow) * VPAD + kc * 8 + bcol) * 4);
                mma_tf32(D[0][0], pa0[0], pa0[1], pa0[2], pa0[3], vb0[0], vb0[1]);
                mma_tf32(D[0][1], pa0[0], pa0[1], pa0[2], pa0[3], vb0[2], vb0[3]);
                mma_tf32(D[0][2], pa0[0], pa0[1], pa0[2], pa0[3], vb1[0], vb1[1]);
                mma_tf32(D[0][3], pa0[0], pa0[1], pa0[2], pa0[3], vb1[2], vb1[3]);
                mma_tf32(D[1][0], pa1[0], pa1[1], pa1[2], pa1[3], vb0[0], vb0[1]);
                mma_tf32(D[1][1], pa1[0], pa1[1], pa1[2], pa1[3], vb0[2], vb0[3]);
                mma_tf32(D[1][2], pa1[0], pa1[1], pa1[2], pa1[3], vb1[0], vb1[1]);
                mma_tf32(D[1][3], pa1[0], pa1[1], pa1[2], pa1[3], vb1[2], vb1[3]);
            }
        }
        __syncthreads();   // sync3: all reads of V(buf^1 target) + P done
                           // before next iteration's prefetch/softmax overwrite
        buf ^= 1;
    }

    // ---- l reduction ----
    l0 += __shfl_xor_sync(0xffffffffu, l0, 1);
    l0 += __shfl_xor_sync(0xffffffffu, l0, 2);
    l1 += __shfl_xor_sync(0xffffffffu, l1, 1);
    l1 += __shfl_xor_sync(0xffffffffu, l1, 2);
    if (tq == 0) {
        atomicAdd(&sL[qb + g], l0);
        atomicAdd(&sL[qb + g + 8], l1);
    }
    __syncthreads();
    if (tid < 64)
        g_pl[sp * NPOS + qbase + tid] = sL[tid];

    // ---- write D partials ----
    #pragma unroll
    for (int qi = 0; qi < 2; qi++) {
        #pragma unroll
        for (int nt = 0; nt < 4; nt++) {
            int col = cq + nt * 8 + 2 * tq;
            int r0 = qbase + qh2 + qi * 16 + g;
            *(float2*)&g_pacc[((size_t)sp * NPOS + r0) * CCH + col] =
                make_float2(D[qi][nt][0], D[qi][nt][1]);
            *(float2*)&g_pacc[((size_t)sp * NPOS + r0 + 8) * CCH + col] =
                make_float2(D[qi][nt][2], D[qi][nt][3]);
        }
    }
}

// ---------------- kernel: combine splits (pure addition) ----------------
__global__ void k_combine() {
    int q = blockIdx.x;
    int c = threadIdx.x;
    float L = 0.f;
    #pragma unroll
    for (int s = 0; s < NSPLIT; s++) L += g_pl[s * NPOS + q];
    float a = 0.f;
    #pragma unroll
    for (int s = 0; s < NSPLIT; s++) a += g_pacc[((size_t)s * NPOS + q) * CCH + c];
    g_av[(size_t)q * CCH + c] = a / L;
}

// ---------------- kernel: output projection y = wa @ av + ba ----------------
__global__ void __launch_bounds__(256) k_ygemm(const float* __restrict__ ba) {
    __shared__ float avs[64 * CCH];
    int tid = threadIdx.x;
    int nbase = blockIdx.x * 64;
    for (int t = tid; t < 64 * (CCH / 4); t += 256) {
        int n = t >> 5;
        int c4 = (t & 31) << 2;
        *(float4*)&avs[n * CCH + c4] = *(const float4*)&g_av[(size_t)(nbase + n) * CCH + c4];
    }
    __syncthreads();
    int c0 = (tid & 31) * 4;
    int n0 = (tid >> 5) * 8;
    float acc[8][4];
    #pragma unroll
    for (int i = 0; i < 8; i++)
        #pragma unroll
        for (int k = 0; k < 4; k++) acc[i][k] = 0.f;
    for (int cc = 0; cc < CCH; cc++) {
        float4 wf = *(const float4*)&g_waT[cc * CCH + c0];
        #pragma unroll
        for (int i = 0; i < 8; i++) {
            float a = avs[(n0 + i) * CCH + cc];
            acc[i][0] += a * wf.x;
            acc[i][1] += a * wf.y;
            acc[i][2] += a * wf.z;
            acc[i][3] += a * wf.w;
        }
    }
    #pragma unroll
    for (int k = 0; k < 4; k++) {
        float b = ba[c0 + k];
        #pragma unroll
        for (int i = 0; i < 8; i++)
            g_y[(size_t)(c0 + k) * NPOS + nbase + n0 + i] = acc[i][k] + b;
    }
}

// ---------------- kernel: per-channel BN stats ----------------
__global__ void k_stats() {
    int c = blockIdx.x;
    int tid = threadIdx.x;
    float s = 0.f, sq = 0.f;
    for (int n = tid; n < NPOS; n += 256) {
        float v = g_y[(size_t)c * NPOS + n];
        s += v; sq += v * v;
    }
    #pragma unroll
    for (int o = 16; o > 0; o >>= 1) {
        s  += __shfl_xor_sync(0xffffffffu, s, o);
        sq += __shfl_xor_sync(0xffffffffu, sq, o);
    }
    __shared__ float ws[8], wqs[8];
    int w = tid >> 5, l = tid & 31;
    if (l == 0) { ws[w] = s; wqs[w] = sq; }
    __syncthreads();
    if (tid == 0) {
        float ts = 0.f, tq2 = 0.f;
        #pragma unroll
        for (int i = 0; i < 8; i++) { ts += ws[i]; tq2 += wqs[i]; }
        float mean = ts / (float)NPOS;
        float var = tq2 / (float)NPOS - mean * mean;
        g_mean[c] = mean;
        g_rstd[c] = rsqrtf(var + 1e-5f);
    }
}

// ---------------- kernel: BN + ReLU + residual ----------------
__global__ void k_final(const float* __restrict__ x,
                        const float* __restrict__ bnw, const float* __restrict__ bnb,
                        float* __restrict__ out) {
    int idx = blockIdx.x * 256 + threadIdx.x;
    int c = idx / NPOS;
    float yv = g_y[idx];
    float o = (yv - g_mean[c]) * g_rstd[c] * bnw[c] + bnb[c];
    out[idx] = fmaxf(o, 0.f) + x[idx];
}

// ---------------- launch ----------------
extern "C" void kernel_launch(void* const* d_in, const int* in_sizes, int n_in,
                              void* d_out, int out_size) {
    const float* x   = (const float*)d_in[0];
    const float* wq  = (const float*)d_in[1];
    const float* bq  = (const float*)d_in[2];
    const float* wk  = (const float*)d_in[3];
    const float* bk  = (const float*)d_in[4];
    const float* wv  = (const float*)d_in[5];
    const float* bv  = (const float*)d_in[6];
    const float* wa  = (const float*)d_in[7];
    const float* ba  = (const float*)d_in[8];
    const float* bnw = (const float*)d_in[9];
    const float* bnb = (const float*)d_in[10];
    float* out = (float*)d_out;

    static int smem_set = 0;
    if (!smem_set) {
        cudaFuncSetAttribute(k_flash_mma, cudaFuncAttributeMaxDynamicSharedMemorySize,
                             FLASH_SMEM);
        smem_set = 1;
    }

    k_transpose_w<<<64, 256>>>(wa);
    k_proj_qk<<<250, 256>>>(x, wq, bq, wk, bk);
    k_proj_v<<<dim3(125, 4), 256>>>(x, wv, bv);
    k_flash_mma<<<dim3(QT, NSPLIT), 256, FLASH_SMEM>>>();
    k_combine<<<NPOS, CCH>>>();
    k_ygemm<<<NPOS / 64, 256>>>(ba);
    k_stats<<<CCH, 256>>>();
    k_final<<<(NPOS * CCH) / 256, 256>>>(x, bnw, bnb, out);
}

// round 9
// speedup vs baseline: 1.6486x; 1.0058x over previous
#include <cuda_runtime.h>
#include <cstdint>

// ---------------- problem constants ----------------
#define NPOS   8000
#define CCH    128
#define CQ     16
#define NSPLIT 5
#define JT_PER 25        // 125 j-tiles / 5 splits
#define QT     125       // q tiles of 64

#define KPAD 20
#define VPAD 68          // V smem pitch ([c][j] layout)
#define PPAD 68

// smem float offsets
#define OFF_Q  0                    // [64][20]
#define OFF_K  1280                 // [2][64][20]
#define OFF_V  3840                 // [2][128][68]
#define OFF_P  21248                // [64][68]
#define OFF_L  25600                // [64]
#define SM_FLOATS 25664
#define FLASH_SMEM (SM_FLOATS * 4)  // 102656 B

// ---------------- device scratch ----------------
__device__ float g_q[NPOS * CQ];            // [n][d], tf32-rounded
__device__ float g_k[NPOS * CQ];            // [n][d], tf32-rounded
__device__ float g_v[(size_t)CCH * NPOS];   // [c][n], tf32-rounded
__device__ float g_waT[CCH * CCH];
__device__ float g_pacc[(size_t)NSPLIT * NPOS * CCH];
__device__ float g_pl[NSPLIT * NPOS];
__device__ float g_y[(size_t)CCH * NPOS];
__device__ float g_sum[CCH], g_sq[CCH];

// ---------------- helpers ----------------
__device__ __forceinline__ uint32_t smem_u32(const void* p) {
    uint32_t a;
    asm("{ .reg .u64 t; cvta.to.shared.u64 t, %1; cvt.u32.u64 %0, t; }" : "=r"(a) : "l"(p));
    return a;
}
__device__ __forceinline__ float rna_tf32(float x) {
    uint32_t t; asm("cvt.rna.tf32.f32 %0, %1;" : "=r"(t) : "f"(x));
    return __uint_as_float(t);
}
__device__ __forceinline__ uint32_t tf32_bits(float x) {
    uint32_t t; asm("cvt.rna.tf32.f32 %0, %1;" : "=r"(t) : "f"(x));
    return t;
}
__device__ __forceinline__ void mma_tf32(float d[4],
                                         uint32_t a0, uint32_t a1, uint32_t a2, uint32_t a3,
                                         uint32_t b0, uint32_t b1) {
    asm volatile("mma.sync.aligned.m16n8k8.row.col.f32.tf32.tf32.f32 "
                 "{%0,%1,%2,%3}, {%4,%5,%6,%7}, {%8,%9}, {%0,%1,%2,%3};"
                 : "+f"(d[0]), "+f"(d[1]), "+f"(d[2]), "+f"(d[3])
                 : "r"(a0), "r"(a1), "r"(a2), "r"(a3), "r"(b0), "r"(b1));
}
__device__ __forceinline__ void ldsm4(uint32_t r[4], uint32_t addr) {
    asm volatile("ldmatrix.sync.aligned.m8n8.x4.shared.b16 {%0,%1,%2,%3}, [%4];"
                 : "=r"(r[0]), "=r"(r[1]), "=r"(r[2]), "=r"(r[3]) : "r"(addr));
}
#define CPA16(dst, src) \
    asm volatile("cp.async.cg.shared.global [%0], [%1], 16;" :: "r"(dst), "l"(src))
#define CP_COMMIT() asm volatile("cp.async.commit_group;" ::: "memory")
#define CP_WAIT1()  asm volatile("cp.async.wait_group 1;" ::: "memory")
#define CP_WAIT0()  asm volatile("cp.async.wait_group 0;" ::: "memory")

// ---------------- kernel: transpose wa + zero stats accumulators ----------------
__global__ void k_transpose_w(const float* __restrict__ wa) {
    int i = blockIdx.x * blockDim.x + threadIdx.x;   // 16384
    if (i < CCH) { g_sum[i] = 0.f; g_sq[i] = 0.f; }
    int r = i >> 7, c = i & 127;
    g_waT[c * CCH + r] = wa[r * CCH + c];
}

// ---------------- kernel: q/k projections (smem weights, 4 outputs/thread) ----------------
__global__ void __launch_bounds__(256) k_proj_qk(const float* __restrict__ x,
                                                 const float* __restrict__ wq,
                                                 const float* __restrict__ bq,
                                                 const float* __restrict__ wk,
                                                 const float* __restrict__ bk) {
    __shared__ float swT[CCH * 32];   // [cc][32 outputs: 16 q | 16 k]
    __shared__ float sb[32];
    const int tid = threadIdx.x;
    for (int i = tid; i < 16 * CCH; i += 256) {
        int d = i >> 7, cc = i & 127;
        swT[cc * 32 + d]      = wq[i];
        swT[cc * 32 + 16 + d] = wk[i];
    }
    if (tid < 16) sb[tid] = bq[tid];
    else if (tid < 32) sb[tid] = bk[tid - 16];
    __syncthreads();

    const int n  = blockIdx.x * 32 + (tid & 31);   // 250 blocks x 32 n
    const int og = tid >> 5;                       // 0..7 -> outputs og*4..og*4+3
    float a0 = sb[og * 4 + 0], a1 = sb[og * 4 + 1];
    float a2 = sb[og * 4 + 2], a3 = sb[og * 4 + 3];
    #pragma unroll 4
    for (int cc = 0; cc < CCH; cc++) {
        float xv = x[cc * NPOS + n];
        float4 w = *(const float4*)&swT[cc * 32 + og * 4];
        a0 += w.x * xv; a1 += w.y * xv; a2 += w.z * xv; a3 += w.w * xv;
    }
    float* o = (og < 4) ? g_q : g_k;
    int d0 = (og < 4) ? og * 4 : (og - 4) * 4;
    o[n * CQ + d0 + 0] = rna_tf32(a0);
    o[n * CQ + d0 + 1] = rna_tf32(a1);
    o[n * CQ + d0 + 2] = rna_tf32(a2);
    o[n * CQ + d0 + 3] = rna_tf32(a3);
}

// ---------------- kernel: v projection -> [c][n], tf32-rounded, smem-tiled ----------------
__global__ void __launch_bounds__(256) k_proj_v(const float* __restrict__ x,
                                                const float* __restrict__ wv,
                                                const float* __restrict__ bv) {
    __shared__ float sw[32 * CCH];              // wv rows cb..cb+31
    const int tid = threadIdx.x;
    const int nb = blockIdx.x * 64;
    const int cb = blockIdx.y * 32;
    for (int i = tid; i < 32 * CCH; i += 256) {
        int r = i >> 7, c = i & 127;
        sw[i] = wv[(cb + r) * CCH + c];
    }
    __syncthreads();
    const int n = nb + (tid & 63);
    const int c0 = (tid >> 6) * 8;
    float acc[8];
    #pragma unroll
    for (int i = 0; i < 8; i++) acc[i] = bv[cb + c0 + i];
    #pragma unroll 4
    for (int cc4 = 0; cc4 < 32; cc4++) {
        float x0 = x[(cc4 * 4 + 0) * NPOS + n];
        float x1 = x[(cc4 * 4 + 1) * NPOS + n];
        float x2 = x[(cc4 * 4 + 2) * NPOS + n];
        float x3 = x[(cc4 * 4 + 3) * NPOS + n];
        #pragma unroll
        for (int i = 0; i < 8; i++) {
            float4 w = *(const float4*)&sw[(c0 + i) * CCH + cc4 * 4];
            acc[i] += w.x * x0 + w.y * x1 + w.z * x2 + w.w * x3;
        }
    }
    #pragma unroll
    for (int i = 0; i < 8; i++)
        g_v[(size_t)(cb + c0 + i) * NPOS + n] = rna_tf32(acc[i]);
}

// ---------------- kernel: flash attention, mma.sync tf32 + ldmatrix ----------------
__global__ void __launch_bounds__(256, 2) k_flash_mma() {
    extern __shared__ float sm[];
    float* sQ = sm + OFF_Q;
    float* sP = sm + OFF_P;
    float* sL = sm + OFF_L;
    const uint32_t smb = smem_u32(sm);

    const int tid  = threadIdx.x;
    const int wid  = tid >> 5;
    const int lane = tid & 31;
    const int g    = lane >> 2;     // groupID (0..7)
    const int tq   = lane & 3;      // threadID_in_group

    const int qt = blockIdx.x, sp = blockIdx.y;
    const int qbase = qt * 64;
    const int jt0 = sp * JT_PER;

    // MMA1/softmax mapping: 4 q-blocks x 2 j-halves
    const int qb = (wid >> 1) * 16;
    const int jh = (wid & 1) * 32;
    // MMA2 mapping: 2 q-halves x 4 c-quarters
    const int qh2 = (wid >> 2) * 32;
    const int cq  = (wid & 3) * 32;

    if (tid < 64) sL[tid] = 0.f;

    // load Q tile: 64 rows x 16 floats
    {
        int j = tid >> 2, seg = tid & 3;
        *(float4*)&sQ[j * KPAD + seg * 4] =
            *(const float4*)&g_q[(qbase + j) * CQ + seg * 4];
    }

    // incremental prefetch pointers (constant strides folded into cp.async)
    const int krow = tid >> 2, kseg = tid & 3;
    const int vc0 = tid >> 4, vj4 = tid & 15;
    const float* srcK = &g_k[(jt0 * 64 + krow) * CQ + kseg * 4];
    const float* srcV = &g_v[(size_t)vc0 * NPOS + jt0 * 64 + vj4 * 4];
    uint32_t dstK[2], dstV[2];
    dstK[0] = smb + (OFF_K + krow * KPAD + kseg * 4) * 4;
    dstK[1] = dstK[0] + 1280 * 4;
    dstV[0] = smb + (OFF_V + vc0 * VPAD + vj4 * 4) * 4;
    dstV[1] = dstV[0] + 8704 * 4;

    auto prefetch = [&](int bufi) {
        CPA16(dstK[bufi], srcK);
        #pragma unroll
        for (int i = 0; i < 8; i++)
            CPA16(dstV[bufi] + i * (16 * VPAD * 4), srcV + (size_t)i * 16 * NPOS);
        CP_COMMIT();
        srcK += 64 * CQ;
        srcV += 64;
    };

    float D[2][4][4];
    #pragma unroll
    for (int qi = 0; qi < 2; qi++)
        #pragma unroll
        for (int nt = 0; nt < 4; nt++)
            #pragma unroll
            for (int k = 0; k < 4; k++) D[qi][nt][k] = 0.f;
    float l0 = 0.f, l1 = 0.f;

    int buf = 0;
    prefetch(0);
    __syncthreads();   // sQ visible before hoisted ldmatrix

    // hoisted Q A-fragments (loop-invariant)
    uint32_t qa[2][4];
    {
        uint32_t base = smb + (OFF_Q + (qb + (lane & 15)) * KPAD + (lane >> 4) * 4) * 4;
        ldsm4(qa[0], base);
        ldsm4(qa[1], base + 8 * 4);
    }

    // per-thread ldmatrix address offsets
    const int arow1 = (lane & 15);             // A chunk row within 16
    const int acol  = (lane >> 4) * 4;         // A chunk col
    const int brow  = (lane & 7) + (lane >> 4) * 8;   // B chunk row within 16
    const int bcol  = (lane & 8) ? 4 : 0;             // B chunk col

    for (int it = 0; it < JT_PER; it++) {
        if (it + 1 < JT_PER) { prefetch(buf ^ 1); CP_WAIT1(); }
        else                 { CP_WAIT0(); }
        __syncthreads();   // sync1: K/V(buf) ready

        // ---- MMA1: S[16q x 32j] per warp ----
        float S[4][4];
        #pragma unroll
        for (int nt = 0; nt < 4; nt++)
            #pragma unroll
            for (int k = 0; k < 4; k++) S[nt][k] = 0.f;

        {
            const uint32_t kbase = smb + (OFF_K + buf * 1280) * 4;
            #pragma unroll
            for (int kc = 0; kc < 2; kc++) {
                uint32_t kb0[4], kb1[4];
                ldsm4(kb0, kbase + ((jh + brow) * KPAD + kc * 8 + bcol) * 4);
                ldsm4(kb1, kbase + ((jh + 16 + brow) * KPAD + kc * 8 + bcol) * 4);
                mma_tf32(S[0], qa[kc][0], qa[kc][1], qa[kc][2], qa[kc][3], kb0[0], kb0[1]);
                mma_tf32(S[1], qa[kc][0], qa[kc][1], qa[kc][2], qa[kc][3], kb0[2], kb0[3]);
                mma_tf32(S[2], qa[kc][0], qa[kc][1], qa[kc][2], qa[kc][3], kb1[0], kb1[1]);
                mma_tf32(S[3], qa[kc][0], qa[kc][1], qa[kc][2], qa[kc][3], kb1[2], kb1[3]);
            }
        }

        // ---- softmax (no max-subtraction) + tf32 convert + store P ----
        #pragma unroll
        for (int nt = 0; nt < 4; nt++) {
            float p0 = __expf(S[nt][0]);
            float p1 = __expf(S[nt][1]);
            float p2 = __expf(S[nt][2]);
            float p3 = __expf(S[nt][3]);
            l0 += p0 + p1;
            l1 += p2 + p3;
            int col = jh + nt * 8 + 2 * tq;
            *(float2*)&sP[(qb + g) * PPAD + col] =
                make_float2(__uint_as_float(tf32_bits(p0)), __uint_as_float(tf32_bits(p1)));
            *(float2*)&sP[(qb + g + 8) * PPAD + col] =
                make_float2(__uint_as_float(tf32_bits(p2)), __uint_as_float(tf32_bits(p3)));
        }
        // sync2 (split): MMA2 of warps 0-3 reads only P rows 0-31 (written by
        // warps 0-3); warps 4-7 likewise rows 32-63.
        if (wid < 4) asm volatile("bar.sync 3, 128;" ::: "memory");
        else         asm volatile("bar.sync 4, 128;" ::: "memory");

        // ---- MMA2: D[32q x 32c] per warp ----
        {
            const uint32_t pbase = smb + OFF_P * 4;
            const uint32_t vbase = smb + (OFF_V + buf * 8704) * 4;
            #pragma unroll
            for (int kc = 0; kc < 8; kc++) {
                uint32_t pa0[4], pa1[4], vb0[4], vb1[4];
                ldsm4(pa0, pbase + ((qh2 + arow1) * PPAD + kc * 8 + acol) * 4);
                ldsm4(pa1, pbase + ((qh2 + 16 + arow1) * PPAD + kc * 8 + acol) * 4);
                ldsm4(vb0, vbase + ((cq + brow) * VPAD + kc * 8 + bcol) * 4);
                ldsm4(vb1, vbase + ((cq + 16 + brow) * VPAD + kc * 8 + bcol) * 4);
                mma_tf32(D[0][0], pa0[0], pa0[1], pa0[2], pa0[3], vb0[0], vb0[1]);
                mma_tf32(D[0][1], pa0[0], pa0[1], pa0[2], pa0[3], vb0[2], vb0[3]);
                mma_tf32(D[0][2], pa0[0], pa0[1], pa0[2], pa0[3], vb1[0], vb1[1]);
                mma_tf32(D[0][3], pa0[0], pa0[1], pa0[2], pa0[3], vb1[2], vb1[3]);
                mma_tf32(D[1][0], pa1[0], pa1[1], pa1[2], pa1[3], vb0[0], vb0[1]);
                mma_tf32(D[1][1], pa1[0], pa1[1], pa1[2], pa1[3], vb0[2], vb0[3]);
                mma_tf32(D[1][2], pa1[0], pa1[1], pa1[2], pa1[3], vb1[0], vb1[1]);
                mma_tf32(D[1][3], pa1[0], pa1[1], pa1[2], pa1[3], vb1[2], vb1[3]);
            }
        }
        __syncthreads();   // sync3: all reads of V(buf) + P done before next
                           // iteration's prefetch/softmax overwrite
        buf ^= 1;
    }

    // ---- l reduction ----
    l0 += __shfl_xor_sync(0xffffffffu, l0, 1);
    l0 += __shfl_xor_sync(0xffffffffu, l0, 2);
    l1 += __shfl_xor_sync(0xffffffffu, l1, 1);
    l1 += __shfl_xor_sync(0xffffffffu, l1, 2);
    if (tq == 0) {
        atomicAdd(&sL[qb + g], l0);
        atomicAdd(&sL[qb + g + 8], l1);
    }
    __syncthreads();
    if (tid < 64)
        g_pl[sp * NPOS + qbase + tid] = sL[tid];

    // ---- write D partials ----
    #pragma unroll
    for (int qi = 0; qi < 2; qi++) {
        #pragma unroll
        for (int nt = 0; nt < 4; nt++) {
            int col = cq + nt * 8 + 2 * tq;
            int r0 = qbase + qh2 + qi * 16 + g;
            *(float2*)&g_pacc[((size_t)sp * NPOS + r0) * CCH + col] =
                make_float2(D[qi][nt][0], D[qi][nt][1]);
            *(float2*)&g_pacc[((size_t)sp * NPOS + r0 + 8) * CCH + col] =
                make_float2(D[qi][nt][2], D[qi][nt][3]);
        }
    }
}

// ---- kernel: fused combine + output projection + BN stat partials ----------
__global__ void __launch_bounds__(256) k_ygemm(const float* __restrict__ ba) {
    __shared__ float avs[64 * CCH];     // 32 KB
    __shared__ float sLr[64];
    __shared__ float ssum[CCH], ssq[CCH];
    const int tid = threadIdx.x;
    const int nbase = blockIdx.x * 64;

    if (tid < 64) {
        float L = 0.f;
        #pragma unroll
        for (int s = 0; s < NSPLIT; s++) L += g_pl[s * NPOS + nbase + tid];
        sLr[tid] = 1.f / L;
    }
    if (tid < CCH) { ssum[tid] = 0.f; ssq[tid] = 0.f; }
    __syncthreads();

    // combine splits directly into the smem tile
    for (int t = tid; t < 64 * (CCH / 4); t += 256) {
        int n = t >> 5;
        int c4 = (t & 31) << 2;
        float4 a = make_float4(0.f, 0.f, 0.f, 0.f);
        #pragma unroll
        for (int s = 0; s < NSPLIT; s++) {
            float4 p = *(const float4*)&g_pacc[((size_t)s * NPOS + nbase + n) * CCH + c4];
            a.x += p.x; a.y += p.y; a.z += p.z; a.w += p.w;
        }
        float r = sLr[n];
        a.x *= r; a.y *= r; a.z *= r; a.w *= r;
        *(float4*)&avs[n * CCH + c4] = a;
    }
    __syncthreads();

    const int c0 = (tid & 31) * 4;
    const int n0 = (tid >> 5) * 8;
    float acc[8][4];
    #pragma unroll
    for (int i = 0; i < 8; i++)
        #pragma unroll
        for (int k = 0; k < 4; k++) acc[i][k] = 0.f;
    for (int cc = 0; cc < CCH; cc++) {
        float4 wf = *(const float4*)&g_waT[cc * CCH + c0];
        #pragma unroll
        for (int i = 0; i < 8; i++) {
            float a = avs[(n0 + i) * CCH + cc];
            acc[i][0] += a * wf.x;
            acc[i][1] += a * wf.y;
            acc[i][2] += a * wf.z;
            acc[i][3] += a * wf.w;
        }
    }
    #pragma unroll
    for (int k = 0; k < 4; k++) {
        float b = ba[c0 + k];
        float cs = 0.f, cq2 = 0.f;
        #pragma unroll
        for (int i = 0; i < 8; i++) {
            float yv = acc[i][k] + b;
            g_y[(size_t)(c0 + k) * NPOS + nbase + n0 + i] = yv;
            cs += yv; cq2 += yv * yv;
        }
        atomicAdd(&ssum[c0 + k], cs);
        atomicAdd(&ssq[c0 + k], cq2);
    }
    __syncthreads();
    if (tid < CCH) {
        atomicAdd(&g_sum[tid], ssum[tid]);
        atomicAdd(&g_sq[tid],  ssq[tid]);
    }
}

// ---------------- kernel: BN (from global sums) + ReLU + residual ----------------
__global__ void k_final(const float* __restrict__ x,
                        const float* __restrict__ bnw, const float* __restrict__ bnb,
                        float* __restrict__ out) {
    const int c = blockIdx.y;
    const int n = blockIdx.x * 256 + threadIdx.x;
    if (n >= NPOS) return;
    const float inv = 1.f / (float)NPOS;
    float mean = g_sum[c] * inv;
    float var = g_sq[c] * inv - mean * mean;
    float rstd = rsqrtf(var + 1e-5f);
    size_t idx = (size_t)c * NPOS + n;
    float yv = g_y[idx];
    float o = (yv - mean) * rstd * bnw[c] + bnb[c];
    out[idx] = fmaxf(o, 0.f) + x[idx];
}

// ---------------- launch ----------------
extern "C" void kernel_launch(void* const* d_in, const int* in_sizes, int n_in,
                              void* d_out, int out_size) {
    const float* x   = (const float*)d_in[0];
    const float* wq  = (const float*)d_in[1];
    const float* bq  = (const float*)d_in[2];
    const float* wk  = (const float*)d_in[3];
    const float* bk  = (const float*)d_in[4];
    const float* wv  = (const float*)d_in[5];
    const float* bv  = (const float*)d_in[6];
    const float* wa  = (const float*)d_in[7];
    const float* ba  = (const float*)d_in[8];
    const float* bnw = (const float*)d_in[9];
    const float* bnb = (const float*)d_in[10];
    float* out = (float*)d_out;

    static int smem_set = 0;
    if (!smem_set) {
        cudaFuncSetAttribute(k_flash_mma, cudaFuncAttributeMaxDynamicSharedMemorySize,
                             FLASH_SMEM);
        smem_set = 1;
    }

    k_transpose_w<<<64, 256>>>(wa);
    k_proj_qk<<<250, 256>>>(x, wq, bq, wk, bk);
    k_proj_v<<<dim3(125, 4), 256>>>(x, wv, bv);
    k_flash_mma<<<dim3(QT, NSPLIT), 256, FLASH_SMEM>>>();
    k_ygemm<<<NPOS / 64, 256>>>(ba);
    k_final<<<dim3(32, CCH), 256>>>(x, bnw, bnb, out);
}

// round 10
// speedup vs baseline: 2.2578x; 1.3696x over previous
#include <cuda_runtime.h>
#include <cuda_fp16.h>
#include <cstdint>

// ---------------- problem constants ----------------
#define NPOS   8000
#define CCH    128
#define CQ     16
#define NSPLIT 5
#define JT_PER 25        // 125 j-tiles / 5 splits
#define QT     125       // q tiles of 64

#define KPAD   20        // K/Q smem pitch (floats)
#define VPITCH 72        // V smem pitch (halfs) -> 144B rows, conflict-free
#define PPITCH 72        // P smem pitch (halfs)

// smem byte offsets
#define OFF_Q  0                    // float [64][20]          5120 B
#define OFF_K  5120                 // float [2][64][20]      10240 B
#define KBUF   5120
#define OFF_V  15360                // half  [2][128][72]     36864 B
#define VBUF   18432
#define OFF_P  52224                // half  [64][72]          9216 B
#define OFF_L  61440                // float [64]               256 B
#define FLASH_SMEM 61696

// ---------------- device scratch ----------------
__device__ float  g_q[NPOS * CQ];            // [n][d], tf32-rounded
__device__ float  g_k[NPOS * CQ];            // [n][d], tf32-rounded
__device__ __half g_v[(size_t)CCH * NPOS];   // [c][n], fp16
__device__ float  g_waT[CCH * CCH];
__device__ float  g_pacc[(size_t)NSPLIT * NPOS * CCH];
__device__ float  g_pl[NSPLIT * NPOS];
__device__ float  g_y[(size_t)CCH * NPOS];
__device__ float  g_sum[CCH], g_sq[CCH];

// ---------------- helpers ----------------
__device__ __forceinline__ uint32_t smem_u32(const void* p) {
    uint32_t a;
    asm("{ .reg .u64 t; cvta.to.shared.u64 t, %1; cvt.u32.u64 %0, t; }" : "=r"(a) : "l"(p));
    return a;
}
__device__ __forceinline__ float rna_tf32(float x) {
    uint32_t t; asm("cvt.rna.tf32.f32 %0, %1;" : "=r"(t) : "f"(x));
    return __uint_as_float(t);
}
__device__ __forceinline__ void mma_tf32(float d[4],
                                         uint32_t a0, uint32_t a1, uint32_t a2, uint32_t a3,
                                         uint32_t b0, uint32_t b1) {
    asm volatile("mma.sync.aligned.m16n8k8.row.col.f32.tf32.tf32.f32 "
                 "{%0,%1,%2,%3}, {%4,%5,%6,%7}, {%8,%9}, {%0,%1,%2,%3};"
                 : "+f"(d[0]), "+f"(d[1]), "+f"(d[2]), "+f"(d[3])
                 : "r"(a0), "r"(a1), "r"(a2), "r"(a3), "r"(b0), "r"(b1));
}
__device__ __forceinline__ void mma_f16(float d[4],
                                        uint32_t a0, uint32_t a1, uint32_t a2, uint32_t a3,
                                        uint32_t b0, uint32_t b1) {
    asm volatile("mma.sync.aligned.m16n8k16.row.col.f32.f16.f16.f32 "
                 "{%0,%1,%2,%3}, {%4,%5,%6,%7}, {%8,%9}, {%0,%1,%2,%3};"
                 : "+f"(d[0]), "+f"(d[1]), "+f"(d[2]), "+f"(d[3])
                 : "r"(a0), "r"(a1), "r"(a2), "r"(a3), "r"(b0), "r"(b1));
}
__device__ __forceinline__ void ldsm4(uint32_t r[4], uint32_t addr) {
    asm volatile("ldmatrix.sync.aligned.m8n8.x4.shared.b16 {%0,%1,%2,%3}, [%4];"
                 : "=r"(r[0]), "=r"(r[1]), "=r"(r[2]), "=r"(r[3]) : "r"(addr));
}
#define CPA16(dst, src) \
    asm volatile("cp.async.cg.shared.global [%0], [%1], 16;" :: "r"(dst), "l"(src))
#define CP_COMMIT() asm volatile("cp.async.commit_group;" ::: "memory")
#define CP_WAIT1()  asm volatile("cp.async.wait_group 1;" ::: "memory")
#define CP_WAIT0()  asm volatile("cp.async.wait_group 0;" ::: "memory")

// ---------------- kernel: transpose wa + zero stats accumulators ----------------
__global__ void k_transpose_w(const float* __restrict__ wa) {
    int i = blockIdx.x * blockDim.x + threadIdx.x;   // 16384
    if (i < CCH) { g_sum[i] = 0.f; g_sq[i] = 0.f; }
    int r = i >> 7, c = i & 127;
    g_waT[c * CCH + r] = wa[r * CCH + c];
}

// ---------------- kernel: q/k projections (smem weights, 4 outputs/thread) ----------------
__global__ void __launch_bounds__(256) k_proj_qk(const float* __restrict__ x,
                                                 const float* __restrict__ wq,
                                                 const float* __restrict__ bq,
                                                 const float* __restrict__ wk,
                                                 const float* __restrict__ bk) {
    __shared__ float swT[CCH * 32];   // [cc][32 outputs: 16 q | 16 k]
    __shared__ float sb[32];
    const int tid = threadIdx.x;
    for (int i = tid; i < 16 * CCH; i += 256) {
        int d = i >> 7, cc = i & 127;
        swT[cc * 32 + d]      = wq[i];
        swT[cc * 32 + 16 + d] = wk[i];
    }
    if (tid < 16) sb[tid] = bq[tid];
    else if (tid < 32) sb[tid] = bk[tid - 16];
    __syncthreads();

    const int n  = blockIdx.x * 32 + (tid & 31);   // 250 blocks x 32 n
    const int og = tid >> 5;                       // 0..7 -> outputs og*4..og*4+3
    float a0 = sb[og * 4 + 0], a1 = sb[og * 4 + 1];
    float a2 = sb[og * 4 + 2], a3 = sb[og * 4 + 3];
    #pragma unroll 4
    for (int cc = 0; cc < CCH; cc++) {
        float xv = x[cc * NPOS + n];
        float4 w = *(const float4*)&swT[cc * 32 + og * 4];
        a0 += w.x * xv; a1 += w.y * xv; a2 += w.z * xv; a3 += w.w * xv;
    }
    float* o = (og < 4) ? g_q : g_k;
    int d0 = (og < 4) ? og * 4 : (og - 4) * 4;
    o[n * CQ + d0 + 0] = rna_tf32(a0);
    o[n * CQ + d0 + 1] = rna_tf32(a1);
    o[n * CQ + d0 + 2] = rna_tf32(a2);
    o[n * CQ + d0 + 3] = rna_tf32(a3);
}

// ---------------- kernel: v projection -> [c][n] fp16, smem-tiled ----------------
__global__ void __launch_bounds__(256) k_proj_v(const float* __restrict__ x,
                                                const float* __restrict__ wv,
                                                const float* __restrict__ bv) {
    __shared__ float sw[32 * CCH];              // wv rows cb..cb+31
    const int tid = threadIdx.x;
    const int nb = blockIdx.x * 64;
    const int cb = blockIdx.y * 32;
    for (int i = tid; i < 32 * CCH; i += 256) {
        int r = i >> 7, c = i & 127;
        sw[i] = wv[(cb + r) * CCH + c];
    }
    __syncthreads();
    const int n = nb + (tid & 63);
    const int c0 = (tid >> 6) * 8;
    float acc[8];
    #pragma unroll
    for (int i = 0; i < 8; i++) acc[i] = bv[cb + c0 + i];
    #pragma unroll 4
    for (int cc4 = 0; cc4 < 32; cc4++) {
        float x0 = x[(cc4 * 4 + 0) * NPOS + n];
        float x1 = x[(cc4 * 4 + 1) * NPOS + n];
        float x2 = x[(cc4 * 4 + 2) * NPOS + n];
        float x3 = x[(cc4 * 4 + 3) * NPOS + n];
        #pragma unroll
        for (int i = 0; i < 8; i++) {
            float4 w = *(const float4*)&sw[(c0 + i) * CCH + cc4 * 4];
            acc[i] += w.x * x0 + w.y * x1 + w.z * x2 + w.w * x3;
        }
    }
    #pragma unroll
    for (int i = 0; i < 8; i++)
        g_v[(size_t)(cb + c0 + i) * NPOS + n] = __float2half_rn(acc[i]);
}

// ---------------- kernel: flash attention, tf32 MMA1 + fp16 MMA2 ----------------
__global__ void __launch_bounds__(256, 2) k_flash_mma() {
    extern __shared__ char smc[];
    float* sQ = (float*)(smc + OFF_Q);
    float* sL = (float*)(smc + OFF_L);
    const uint32_t smb = smem_u32(smc);

    const int tid  = threadIdx.x;
    const int wid  = tid >> 5;
    const int lane = tid & 31;
    const int g    = lane >> 2;     // groupID (0..7)
    const int tq   = lane & 3;      // threadID_in_group

    const int qt = blockIdx.x, sp = blockIdx.y;
    const int qbase = qt * 64;
    const int jt0 = sp * JT_PER;

    // MMA1/softmax mapping: 4 q-blocks x 2 j-halves
    const int qb = (wid >> 1) * 16;
    const int jh = (wid & 1) * 32;
    // MMA2 mapping: 2 q-halves x 4 c-quarters
    const int qh2 = (wid >> 2) * 32;
    const int cq  = (wid & 3) * 32;

    if (tid < 64) sL[tid] = 0.f;

    // load Q tile: 64 rows x 16 floats
    {
        int j = tid >> 2, seg = tid & 3;
        *(float4*)&sQ[j * KPAD + seg * 4] =
            *(const float4*)&g_q[(qbase + j) * CQ + seg * 4];
    }

    // prefetch pointers
    const int krow = tid >> 2, kseg = tid & 3;
    const int vc0 = tid >> 3, vj16 = tid & 7;      // c 0..31, j-chunk 0..7
    const float*  srcK = &g_k[(jt0 * 64 + krow) * CQ + kseg * 4];
    const __half* srcV = &g_v[(size_t)vc0 * NPOS + jt0 * 64 + vj16 * 8];
    uint32_t dstK[2], dstV[2];
    dstK[0] = smb + OFF_K + (uint32_t)(krow * KPAD + kseg * 4) * 4;
    dstK[1] = dstK[0] + KBUF;
    dstV[0] = smb + OFF_V + (uint32_t)(vc0 * VPITCH + vj16 * 8) * 2;
    dstV[1] = dstV[0] + VBUF;

    auto prefetch = [&](int bufi) {
        CPA16(dstK[bufi], srcK);
        #pragma unroll
        for (int i = 0; i < 4; i++)      // 4 x (32 c-rows)
            CPA16(dstV[bufi] + i * (32 * VPITCH * 2), srcV + (size_t)i * 32 * NPOS);
        CP_COMMIT();
        srcK += 64 * CQ;
        srcV += 64;
    };

    float D[2][4][4];
    #pragma unroll
    for (int qi = 0; qi < 2; qi++)
        #pragma unroll
        for (int nt = 0; nt < 4; nt++)
            #pragma unroll
            for (int k = 0; k < 4; k++) D[qi][nt][k] = 0.f;
    float l0 = 0.f, l1 = 0.f;

    int buf = 0;
    prefetch(0);
    __syncthreads();   // sQ visible before hoisted ldmatrix

    // hoisted Q A-fragments (loop-invariant, tf32)
    uint32_t qa[2][4];
    {
        uint32_t base = smb + OFF_Q + (uint32_t)((qb + (lane & 15)) * KPAD + (lane >> 4) * 4) * 4;
        ldsm4(qa[0], base);
        ldsm4(qa[1], base + 8 * 4);
    }

    // tf32 B (K) ldmatrix offsets
    const int brow = (lane & 7) + (lane >> 4) * 8;
    const int bcol = (lane & 8) ? 4 : 0;
    // fp16 MMA2 ldmatrix per-thread byte offsets
    const uint32_t aoff = (uint32_t)((lane & 15) * PPITCH + (lane >> 4) * 8) * 2;
    const uint32_t boff = (uint32_t)(((lane & 7) + ((lane >> 4) * 8)) * VPITCH
                                     + ((lane >> 3) & 1) * 8) * 2;

    for (int it = 0; it < JT_PER; it++) {
        if (it + 1 < JT_PER) { prefetch(buf ^ 1); CP_WAIT1(); }
        else                 { CP_WAIT0(); }
        __syncthreads();   // sync1: K/V(buf) ready

        // ---- MMA1 (tf32): S[16q x 32j] per warp ----
        float S[4][4];
        #pragma unroll
        for (int nt = 0; nt < 4; nt++)
            #pragma unroll
            for (int k = 0; k < 4; k++) S[nt][k] = 0.f;
        {
            const uint32_t kbase = smb + OFF_K + buf * KBUF;
            #pragma unroll
            for (int kc = 0; kc < 2; kc++) {
                uint32_t kb0[4], kb1[4];
                ldsm4(kb0, kbase + (uint32_t)((jh + brow) * KPAD + kc * 8 + bcol) * 4);
                ldsm4(kb1, kbase + (uint32_t)((jh + 16 + brow) * KPAD + kc * 8 + bcol) * 4);
                mma_tf32(S[0], qa[kc][0], qa[kc][1], qa[kc][2], qa[kc][3], kb0[0], kb0[1]);
                mma_tf32(S[1], qa[kc][0], qa[kc][1], qa[kc][2], qa[kc][3], kb0[2], kb0[3]);
                mma_tf32(S[2], qa[kc][0], qa[kc][1], qa[kc][2], qa[kc][3], kb1[0], kb1[1]);
                mma_tf32(S[3], qa[kc][0], qa[kc][1], qa[kc][2], qa[kc][3], kb1[2], kb1[3]);
            }
        }

        // ---- softmax (no max-subtraction) + fp16 pack + store P ----
        #pragma unroll
        for (int nt = 0; nt < 4; nt++) {
            float p0 = __expf(S[nt][0]);
            float p1 = __expf(S[nt][1]);
            float p2 = __expf(S[nt][2]);
            float p3 = __expf(S[nt][3]);
            l0 += p0 + p1;
            l1 += p2 + p3;
            int col = jh + nt * 8 + 2 * tq;
            *(__half2*)(smc + OFF_P + ((qb + g) * PPITCH + col) * 2) =
                __floats2half2_rn(p0, p1);
            *(__half2*)(smc + OFF_P + ((qb + g + 8) * PPITCH + col) * 2) =
                __floats2half2_rn(p2, p3);
        }
        // sync2 (split): MMA2 of warps 0-3 reads only P rows 0-31 (written by
        // warps 0-3); warps 4-7 likewise rows 32-63.
        if (wid < 4) asm volatile("bar.sync 3, 128;" ::: "memory");
        else         asm volatile("bar.sync 4, 128;" ::: "memory");

        // ---- MMA2 (fp16 k16): D[32q x 32c] per warp, 4 kc x 8 mma ----
        {
            const uint32_t pbase = smb + OFF_P;
            const uint32_t vbase = smb + OFF_V + buf * VBUF;
            #pragma unroll
            for (int kc = 0; kc < 4; kc++) {
                uint32_t pa0[4], pa1[4], vb0[4], vb1[4];
                ldsm4(pa0, pbase + (uint32_t)(qh2 * PPITCH) * 2 + kc * 32 + aoff);
                ldsm4(pa1, pbase + (uint32_t)((qh2 + 16) * PPITCH) * 2 + kc * 32 + aoff);
                ldsm4(vb0, vbase + (uint32_t)(cq * VPITCH) * 2 + kc * 32 + boff);
                ldsm4(vb1, vbase + (uint32_t)((cq + 16) * VPITCH) * 2 + kc * 32 + boff);
                mma_f16(D[0][0], pa0[0], pa0[1], pa0[2], pa0[3], vb0[0], vb0[1]);
                mma_f16(D[0][1], pa0[0], pa0[1], pa0[2], pa0[3], vb0[2], vb0[3]);
                mma_f16(D[0][2], pa0[0], pa0[1], pa0[2], pa0[3], vb1[0], vb1[1]);
                mma_f16(D[0][3], pa0[0], pa0[1], pa0[2], pa0[3], vb1[2], vb1[3]);
                mma_f16(D[1][0], pa1[0], pa1[1], pa1[2], pa1[3], vb0[0], vb0[1]);
                mma_f16(D[1][1], pa1[0], pa1[1], pa1[2], pa1[3], vb0[2], vb0[3]);
                mma_f16(D[1][2], pa1[0], pa1[1], pa1[2], pa1[3], vb1[0], vb1[1]);
                mma_f16(D[1][3], pa1[0], pa1[1], pa1[2], pa1[3], vb1[2], vb1[3]);
            }
        }
        __syncthreads();   // sync3: all reads of V(buf) + P done before next
                           // iteration's prefetch/softmax overwrite
        buf ^= 1;
    }

    // ---- l reduction ----
    l0 += __shfl_xor_sync(0xffffffffu, l0, 1);
    l0 += __shfl_xor_sync(0xffffffffu, l0, 2);
    l1 += __shfl_xor_sync(0xffffffffu, l1, 1);
    l1 += __shfl_xor_sync(0xffffffffu, l1, 2);
    if (tq == 0) {
        atomicAdd(&sL[qb + g], l0);
        atomicAdd(&sL[qb + g + 8], l1);
    }
    __syncthreads();
    if (tid < 64)
        g_pl[sp * NPOS + qbase + tid] = sL[tid];

    // ---- write D partials ----
    #pragma unroll
    for (int qi = 0; qi < 2; qi++) {
        #pragma unroll
        for (int nt = 0; nt < 4; nt++) {
            int col = cq + nt * 8 + 2 * tq;
            int r0 = qbase + qh2 + qi * 16 + g;
            *(float2*)&g_pacc[((size_t)sp * NPOS + r0) * CCH + col] =
                make_float2(D[qi][nt][0], D[qi][nt][1]);
            *(float2*)&g_pacc[((size_t)sp * NPOS + r0 + 8) * CCH + col] =
                make_float2(D[qi][nt][2], D[qi][nt][3]);
        }
    }
}

// ---- kernel: fused combine + output projection + BN stat partials ----------
__global__ void __launch_bounds__(256) k_ygemm(const float* __restrict__ ba) {
    __shared__ float avs[64 * CCH];     // 32 KB
    __shared__ float sLr[64];
    __shared__ float ssum[CCH], ssq[CCH];
    const int tid = threadIdx.x;
    const int nbase = blockIdx.x * 64;

    if (tid < 64) {
        float L = 0.f;
        #pragma unroll
        for (int s = 0; s < NSPLIT; s++) L += g_pl[s * NPOS + nbase + tid];
        sLr[tid] = 1.f / L;
    }
    if (tid < CCH) { ssum[tid] = 0.f; ssq[tid] = 0.f; }
    __syncthreads();

    // combine splits directly into the smem tile
    for (int t = tid; t < 64 * (CCH / 4); t += 256) {
        int n = t >> 5;
        int c4 = (t & 31) << 2;
        float4 a = make_float4(0.f, 0.f, 0.f, 0.f);
        #pragma unroll
        for (int s = 0; s < NSPLIT; s++) {
            float4 p = *(const float4*)&g_pacc[((size_t)s * NPOS + nbase + n) * CCH + c4];
            a.x += p.x; a.y += p.y; a.z += p.z; a.w += p.w;
        }
        float r = sLr[n];
        a.x *= r; a.y *= r; a.z *= r; a.w *= r;
        *(float4*)&avs[n * CCH + c4] = a;
    }
    __syncthreads();

    const int c0 = (tid & 31) * 4;
    const int n0 = (tid >> 5) * 8;
    float acc[8][4];
    #pragma unroll
    for (int i = 0; i < 8; i++)
        #pragma unroll
        for (int k = 0; k < 4; k++) acc[i][k] = 0.f;
    for (int cc = 0; cc < CCH; cc++) {
        float4 wf = *(const float4*)&g_waT[cc * CCH + c0];
        #pragma unroll
        for (int i = 0; i < 8; i++) {
            float a = avs[(n0 + i) * CCH + cc];
            acc[i][0] += a * wf.x;
            acc[i][1] += a * wf.y;
            acc[i][2] += a * wf.z;
            acc[i][3] += a * wf.w;
        }
    }
    #pragma unroll
    for (int k = 0; k < 4; k++) {
        float b = ba[c0 + k];
        float cs = 0.f, cq2 = 0.f;
        #pragma unroll
        for (int i = 0; i < 8; i++) {
            float yv = acc[i][k] + b;
            g_y[(size_t)(c0 + k) * NPOS + nbase + n0 + i] = yv;
            cs += yv; cq2 += yv * yv;
        }
        atomicAdd(&ssum[c0 + k], cs);
        atomicAdd(&ssq[c0 + k], cq2);
    }
    __syncthreads();
    if (tid < CCH) {
        atomicAdd(&g_sum[tid], ssum[tid]);
        atomicAdd(&g_sq[tid],  ssq[tid]);
    }
}

// ---------------- kernel: BN (from global sums) + ReLU + residual ----------------
__global__ void k_final(const float* __restrict__ x,
                        const float* __restrict__ bnw, const float* __restrict__ bnb,
                        float* __restrict__ out) {
    const int c = blockIdx.y;
    const int n = blockIdx.x * 256 + threadIdx.x;
    if (n >= NPOS) return;
    const float inv = 1.f / (float)NPOS;
    float mean = g_sum[c] * inv;
    float var = g_sq[c] * inv - mean * mean;
    float rstd = rsqrtf(var + 1e-5f);
    size_t idx = (size_t)c * NPOS + n;
    float yv = g_y[idx];
    float o = (yv - mean) * rstd * bnw[c] + bnb[c];
    out[idx] = fmaxf(o, 0.f) + x[idx];
}

// ---------------- launch ----------------
extern "C" void kernel_launch(void* const* d_in, const int* in_sizes, int n_in,
                              void* d_out, int out_size) {
    const float* x   = (const float*)d_in[0];
    const float* wq  = (const float*)d_in[1];
    const float* bq  = (const float*)d_in[2];
    const float* wk  = (const float*)d_in[3];
    const float* bk  = (const float*)d_in[4];
    const float* wv  = (const float*)d_in[5];
    const float* bv  = (const float*)d_in[6];
    const float* wa  = (const float*)d_in[7];
    const float* ba  = (const float*)d_in[8];
    const float* bnw = (const float*)d_in[9];
    const float* bnb = (const float*)d_in[10];
    float* out = (float*)d_out;

    static int smem_set = 0;
    if (!smem_set) {
        cudaFuncSetAttribute(k_flash_mma, cudaFuncAttributeMaxDynamicSharedMemorySize,
                             FLASH_SMEM);
        smem_set = 1;
    }

    k_transpose_w<<<64, 256>>>(wa);
    k_proj_qk<<<250, 256>>>(x, wq, bq, wk, bk);
    k_proj_v<<<dim3(125, 4), 256>>>(x, wv, bv);
    k_flash_mma<<<dim3(QT, NSPLIT), 256, FLASH_SMEM>>>();
    k_ygemm<<<NPOS / 64, 256>>>(ba);
    k_final<<<dim3(32, CCH), 256>>>(x, bnw, bnb, out);
}

// round 11
// speedup vs baseline: 2.3840x; 1.0559x over previous
#include <cuda_runtime.h>
#include <cuda_fp16.h>
#include <cstdint>

// ---------------- problem constants ----------------
#define NPOS   8000
#define CCH    128
#define CQ     16
#define NSPLIT 5
#define JT_PER 25        // 125 j-tiles / 5 splits
#define QT     125       // q tiles of 64

#define QKPITCH 24       // Q/K smem pitch (halfs) -> 48B rows, ldsm conflict-free
#define VPITCH  72       // V smem pitch (halfs) -> 144B rows, conflict-free
#define PPITCH  72       // P smem pitch (halfs)

// smem byte offsets
#define OFF_Q  0                    // half [64][24]           3072 B
#define OFF_K  3072                 // half [2][64][24]        6144 B
#define KBUF   3072
#define OFF_V  9216                 // half [2][128][72]      36864 B
#define VBUF   18432
#define OFF_P  46080                // half [64][72]           9216 B
#define OFF_L  55296                // float [64]               256 B
#define FLASH_SMEM 55808

// ---------------- device scratch ----------------
__device__ __half g_q[NPOS * CQ];            // [n][d], fp16
__device__ __half g_k[NPOS * CQ];            // [n][d], fp16
__device__ __half g_v[(size_t)CCH * NPOS];   // [c][n], fp16
__device__ float  g_waT[CCH * CCH];
__device__ float  g_pacc[(size_t)NSPLIT * NPOS * CCH];
__device__ float  g_pl[NSPLIT * NPOS];
__device__ float  g_y[(size_t)CCH * NPOS];
__device__ float  g_sum[CCH], g_sq[CCH];

// ---------------- helpers ----------------
__device__ __forceinline__ uint32_t smem_u32(const void* p) {
    uint32_t a;
    asm("{ .reg .u64 t; cvta.to.shared.u64 t, %1; cvt.u32.u64 %0, t; }" : "=r"(a) : "l"(p));
    return a;
}
__device__ __forceinline__ void mma_f16(float d[4],
                                        uint32_t a0, uint32_t a1, uint32_t a2, uint32_t a3,
                                        uint32_t b0, uint32_t b1) {
    asm volatile("mma.sync.aligned.m16n8k16.row.col.f32.f16.f16.f32 "
                 "{%0,%1,%2,%3}, {%4,%5,%6,%7}, {%8,%9}, {%0,%1,%2,%3};"
                 : "+f"(d[0]), "+f"(d[1]), "+f"(d[2]), "+f"(d[3])
                 : "r"(a0), "r"(a1), "r"(a2), "r"(a3), "r"(b0), "r"(b1));
}
__device__ __forceinline__ void ldsm4(uint32_t r[4], uint32_t addr) {
    asm volatile("ldmatrix.sync.aligned.m8n8.x4.shared.b16 {%0,%1,%2,%3}, [%4];"
                 : "=r"(r[0]), "=r"(r[1]), "=r"(r[2]), "=r"(r[3]) : "r"(addr));
}
#define CPA16(dst, src) \
    asm volatile("cp.async.cg.shared.global [%0], [%1], 16;" :: "r"(dst), "l"(src))
#define CP_COMMIT() asm volatile("cp.async.commit_group;" ::: "memory")
#define CP_WAIT1()  asm volatile("cp.async.wait_group 1;" ::: "memory")
#define CP_WAIT0()  asm volatile("cp.async.wait_group 0;" ::: "memory")

// ---------------- kernel: transpose wa + zero stats accumulators ----------------
__global__ void k_transpose_w(const float* __restrict__ wa) {
    int i = blockIdx.x * blockDim.x + threadIdx.x;   // 16384
    if (i < CCH) { g_sum[i] = 0.f; g_sq[i] = 0.f; }
    int r = i >> 7, c = i & 127;
    g_waT[c * CCH + r] = wa[r * CCH + c];
}

// ---------------- kernel: q/k projections (smem weights, 4 outputs/thread) ----------------
__global__ void __launch_bounds__(256) k_proj_qk(const float* __restrict__ x,
                                                 const float* __restrict__ wq,
                                                 const float* __restrict__ bq,
                                                 const float* __restrict__ wk,
                                                 const float* __restrict__ bk) {
    __shared__ float swT[CCH * 32];   // [cc][32 outputs: 16 q | 16 k]
    __shared__ float sb[32];
    const int tid = threadIdx.x;
    for (int i = tid; i < 16 * CCH; i += 256) {
        int d = i >> 7, cc = i & 127;
        swT[cc * 32 + d]      = wq[i];
        swT[cc * 32 + 16 + d] = wk[i];
    }
    if (tid < 16) sb[tid] = bq[tid];
    else if (tid < 32) sb[tid] = bk[tid - 16];
    __syncthreads();

    const int n  = blockIdx.x * 32 + (tid & 31);   // 250 blocks x 32 n
    const int og = tid >> 5;                       // 0..7 -> outputs og*4..og*4+3
    float a0 = sb[og * 4 + 0], a1 = sb[og * 4 + 1];
    float a2 = sb[og * 4 + 2], a3 = sb[og * 4 + 3];
    #pragma unroll 4
    for (int cc = 0; cc < CCH; cc++) {
        float xv = x[cc * NPOS + n];
        float4 w = *(const float4*)&swT[cc * 32 + og * 4];
        a0 += w.x * xv; a1 += w.y * xv; a2 += w.z * xv; a3 += w.w * xv;
    }
    __half* o = (og < 4) ? g_q : g_k;
    int d0 = (og < 4) ? og * 4 : (og - 4) * 4;
    o[n * CQ + d0 + 0] = __float2half_rn(a0);
    o[n * CQ + d0 + 1] = __float2half_rn(a1);
    o[n * CQ + d0 + 2] = __float2half_rn(a2);
    o[n * CQ + d0 + 3] = __float2half_rn(a3);
}

// ---------------- kernel: v projection -> [c][n] fp16, smem-tiled ----------------
__global__ void __launch_bounds__(256) k_proj_v(const float* __restrict__ x,
                                                const float* __restrict__ wv,
                                                const float* __restrict__ bv) {
    __shared__ float sw[32 * CCH];              // wv rows cb..cb+31
    const int tid = threadIdx.x;
    const int nb = blockIdx.x * 64;
    const int cb = blockIdx.y * 32;
    for (int i = tid; i < 32 * CCH; i += 256) {
        int r = i >> 7, c = i & 127;
        sw[i] = wv[(cb + r) * CCH + c];
    }
    __syncthreads();
    const int n = nb + (tid & 63);
    const int c0 = (tid >> 6) * 8;
    float acc[8];
    #pragma unroll
    for (int i = 0; i < 8; i++) acc[i] = bv[cb + c0 + i];
    #pragma unroll 4
    for (int cc4 = 0; cc4 < 32; cc4++) {
        float x0 = x[(cc4 * 4 + 0) * NPOS + n];
        float x1 = x[(cc4 * 4 + 1) * NPOS + n];
        float x2 = x[(cc4 * 4 + 2) * NPOS + n];
        float x3 = x[(cc4 * 4 + 3) * NPOS + n];
        #pragma unroll
        for (int i = 0; i < 8; i++) {
            float4 w = *(const float4*)&sw[(c0 + i) * CCH + cc4 * 4];
            acc[i] += w.x * x0 + w.y * x1 + w.z * x2 + w.w * x3;
        }
    }
    #pragma unroll
    for (int i = 0; i < 8; i++)
        g_v[(size_t)(cb + c0 + i) * NPOS + n] = __float2half_rn(acc[i]);
}

// ---------------- kernel: flash attention, all-fp16 MMA ----------------
__global__ void __launch_bounds__(256, 2) k_flash_mma() {
    extern __shared__ char smc[];
    float* sL = (float*)(smc + OFF_L);
    const uint32_t smb = smem_u32(smc);

    const int tid  = threadIdx.x;
    const int wid  = tid >> 5;
    const int lane = tid & 31;
    const int g    = lane >> 2;     // groupID (0..7)
    const int tq   = lane & 3;      // threadID_in_group

    const int qt = blockIdx.x, sp = blockIdx.y;
    const int qbase = qt * 64;
    const int jt0 = sp * JT_PER;

    // MMA1/softmax mapping: 4 q-blocks x 2 j-halves
    const int qb = (wid >> 1) * 16;
    const int jh = (wid & 1) * 32;
    // MMA2 mapping: 2 q-halves x 4 c-quarters
    const int qh2 = (wid >> 2) * 32;
    const int cq  = (wid & 3) * 32;

    if (tid < 64) sL[tid] = 0.f;

    // load Q tile: 64 rows x 16 halfs (32B rows -> 128 x 16B chunks)
    if (tid < 128) {
        int row = tid >> 1, seg = tid & 1;
        *(uint4*)(smc + OFF_Q + row * (QKPITCH * 2) + seg * 16) =
            *(const uint4*)&g_q[(qbase + row) * CQ + seg * 8];
    }

    // prefetch pointers
    const int krow = tid >> 1, kseg = tid & 1;     // tid<128 only
    const int vc0 = tid >> 3, vj16 = tid & 7;
    const __half* srcK = &g_k[(jt0 * 64 + krow) * CQ + kseg * 8];
    const __half* srcV = &g_v[(size_t)vc0 * NPOS + jt0 * 64 + vj16 * 8];
    uint32_t dstK[2], dstV[2];
    dstK[0] = smb + OFF_K + (uint32_t)(krow * QKPITCH + kseg * 8) * 2;
    dstK[1] = dstK[0] + KBUF;
    dstV[0] = smb + OFF_V + (uint32_t)(vc0 * VPITCH + vj16 * 8) * 2;
    dstV[1] = dstV[0] + VBUF;

    auto prefetch = [&](int bufi) {
        if (tid < 128) CPA16(dstK[bufi], srcK);
        #pragma unroll
        for (int i = 0; i < 4; i++)      // 4 x (32 c-rows)
            CPA16(dstV[bufi] + i * (32 * VPITCH * 2), srcV + (size_t)i * 32 * NPOS);
        CP_COMMIT();
        srcK += 64 * CQ;
        srcV += 64;
    };

    float D[2][4][4];
    #pragma unroll
    for (int qi = 0; qi < 2; qi++)
        #pragma unroll
        for (int nt = 0; nt < 4; nt++)
            #pragma unroll
            for (int k = 0; k < 4; k++) D[qi][nt][k] = 0.f;
    float l0 = 0.f, l1 = 0.f;

    int buf = 0;
    prefetch(0);
    __syncthreads();   // Q visible before hoisted ldmatrix

    // hoisted Q A-fragment (loop-invariant, fp16, one ldsm.x4)
    uint32_t qa[4];
    ldsm4(qa, smb + OFF_Q + (uint32_t)((qb + (lane & 15)) * QKPITCH + (lane >> 4) * 8) * 2);

    // B-frag ldsm byte offsets (fp16, shared by K and V patterns)
    const uint32_t bK = (uint32_t)(((lane & 7) + ((lane >> 4) * 8)) * QKPITCH
                                   + ((lane >> 3) & 1) * 8) * 2;
    const uint32_t aoff = (uint32_t)((lane & 15) * PPITCH + (lane >> 4) * 8) * 2;
    const uint32_t boff = (uint32_t)(((lane & 7) + ((lane >> 4) * 8)) * VPITCH
                                     + ((lane >> 3) & 1) * 8) * 2;

    for (int it = 0; it < JT_PER; it++) {
        if (it + 1 < JT_PER) { prefetch(buf ^ 1); CP_WAIT1(); }
        else                 { CP_WAIT0(); }
        __syncthreads();   // sync1: K/V(buf) ready

        // ---- MMA1 (fp16 k16): S[16q x 32j] per warp, 2 ldsm + 4 mma ----
        float S[4][4];
        #pragma unroll
        for (int nt = 0; nt < 4; nt++)
            #pragma unroll
            for (int k = 0; k < 4; k++) S[nt][k] = 0.f;
        {
            const uint32_t kbase = smb + OFF_K + buf * KBUF;
            uint32_t kb0[4], kb1[4];
            ldsm4(kb0, kbase + (uint32_t)(jh * QKPITCH) * 2 + bK);
            ldsm4(kb1, kbase + (uint32_t)((jh + 16) * QKPITCH) * 2 + bK);
            mma_f16(S[0], qa[0], qa[1], qa[2], qa[3], kb0[0], kb0[1]);
            mma_f16(S[1], qa[0], qa[1], qa[2], qa[3], kb0[2], kb0[3]);
            mma_f16(S[2], qa[0], qa[1], qa[2], qa[3], kb1[0], kb1[1]);
            mma_f16(S[3], qa[0], qa[1], qa[2], qa[3], kb1[2], kb1[3]);
        }

        // ---- softmax (no max-subtraction) + fp16 pack + store P ----
        #pragma unroll
        for (int nt = 0; nt < 4; nt++) {
            float p0 = __expf(S[nt][0]);
            float p1 = __expf(S[nt][1]);
            float p2 = __expf(S[nt][2]);
            float p3 = __expf(S[nt][3]);
            l0 += p0 + p1;
            l1 += p2 + p3;
            int col = jh + nt * 8 + 2 * tq;
            *(__half2*)(smc + OFF_P + ((qb + g) * PPITCH + col) * 2) =
                __floats2half2_rn(p0, p1);
            *(__half2*)(smc + OFF_P + ((qb + g + 8) * PPITCH + col) * 2) =
                __floats2half2_rn(p2, p3);
        }
        // sync2 (split): MMA2 of warps 0-3 reads only P rows 0-31 (written by
        // warps 0-3); warps 4-7 likewise rows 32-63.
        if (wid < 4) asm volatile("bar.sync 3, 128;" ::: "memory");
        else         asm volatile("bar.sync 4, 128;" ::: "memory");

        // ---- MMA2 (fp16 k16): D[32q x 32c] per warp, 4 kc x 8 mma ----
        {
            const uint32_t pbase = smb + OFF_P;
            const uint32_t vbase = smb + OFF_V + buf * VBUF;
            #pragma unroll
            for (int kc = 0; kc < 4; kc++) {
                uint32_t pa0[4], pa1[4], vb0[4], vb1[4];
                ldsm4(pa0, pbase + (uint32_t)(qh2 * PPITCH) * 2 + kc * 32 + aoff);
                ldsm4(pa1, pbase + (uint32_t)((qh2 + 16) * PPITCH) * 2 + kc * 32 + aoff);
                ldsm4(vb0, vbase + (uint32_t)(cq * VPITCH) * 2 + kc * 32 + boff);
                ldsm4(vb1, vbase + (uint32_t)((cq + 16) * VPITCH) * 2 + kc * 32 + boff);
                mma_f16(D[0][0], pa0[0], pa0[1], pa0[2], pa0[3], vb0[0], vb0[1]);
                mma_f16(D[0][1], pa0[0], pa0[1], pa0[2], pa0[3], vb0[2], vb0[3]);
                mma_f16(D[0][2], pa0[0], pa0[1], pa0[2], pa0[3], vb1[0], vb1[1]);
                mma_f16(D[0][3], pa0[0], pa0[1], pa0[2], pa0[3], vb1[2], vb1[3]);
                mma_f16(D[1][0], pa1[0], pa1[1], pa1[2], pa1[3], vb0[0], vb0[1]);
                mma_f16(D[1][1], pa1[0], pa1[1], pa1[2], pa1[3], vb0[2], vb0[3]);
                mma_f16(D[1][2], pa1[0], pa1[1], pa1[2], pa1[3], vb1[0], vb1[1]);
                mma_f16(D[1][3], pa1[0], pa1[1], pa1[2], pa1[3], vb1[2], vb1[3]);
            }
        }
        __syncthreads();   // sync3: all reads of V(buf) + P done before next
                           // iteration's prefetch/softmax overwrite
        buf ^= 1;
    }

    // ---- l reduction ----
    l0 += __shfl_xor_sync(0xffffffffu, l0, 1);
    l0 += __shfl_xor_sync(0xffffffffu, l0, 2);
    l1 += __shfl_xor_sync(0xffffffffu, l1, 1);
    l1 += __shfl_xor_sync(0xffffffffu, l1, 2);
    if (tq == 0) {
        atomicAdd(&sL[qb + g], l0);
        atomicAdd(&sL[qb + g + 8], l1);
    }
    __syncthreads();
    if (tid < 64)
        g_pl[sp * NPOS + qbase + tid] = sL[tid];

    // ---- write D partials ----
    #pragma unroll
    for (int qi = 0; qi < 2; qi++) {
        #pragma unroll
        for (int nt = 0; nt < 4; nt++) {
            int col = cq + nt * 8 + 2 * tq;
            int r0 = qbase + qh2 + qi * 16 + g;
            *(float2*)&g_pacc[((size_t)sp * NPOS + r0) * CCH + col] =
                make_float2(D[qi][nt][0], D[qi][nt][1]);
            *(float2*)&g_pacc[((size_t)sp * NPOS + r0 + 8) * CCH + col] =
                make_float2(D[qi][nt][2], D[qi][nt][3]);
        }
    }
}

// ---- kernel: fused combine + output projection + BN stat partials ----------
__global__ void __launch_bounds__(256) k_ygemm(const float* __restrict__ ba) {
    __shared__ float avs[64 * CCH];     // 32 KB
    __shared__ float sLr[64];
    __shared__ float ssum[CCH], ssq[CCH];
    const int tid = threadIdx.x;
    const int nbase = blockIdx.x * 64;

    if (tid < 64) {
        float L = 0.f;
        #pragma unroll
        for (int s = 0; s < NSPLIT; s++) L += g_pl[s * NPOS + nbase + tid];
        sLr[tid] = 1.f / L;
    }
    if (tid < CCH) { ssum[tid] = 0.f; ssq[tid] = 0.f; }
    __syncthreads();

    // combine splits directly into the smem tile
    for (int t = tid; t < 64 * (CCH / 4); t += 256) {
        int n = t >> 5;
        int c4 = (t & 31) << 2;
        float4 a = make_float4(0.f, 0.f, 0.f, 0.f);
        #pragma unroll
        for (int s = 0; s < NSPLIT; s++) {
            float4 p = *(const float4*)&g_pacc[((size_t)s * NPOS + nbase + n) * CCH + c4];
            a.x += p.x; a.y += p.y; a.z += p.z; a.w += p.w;
        }
        float r = sLr[n];
        a.x *= r; a.y *= r; a.z *= r; a.w *= r;
        *(float4*)&avs[n * CCH + c4] = a;
    }
    __syncthreads();

    const int c0 = (tid & 31) * 4;
    const int n0 = (tid >> 5) * 8;
    float acc[8][4];
    #pragma unroll
    for (int i = 0; i < 8; i++)
        #pragma unroll
        for (int k = 0; k < 4; k++) acc[i][k] = 0.f;
    #pragma unroll 2
    for (int cc = 0; cc < CCH; cc += 4) {
        float4 w0 = *(const float4*)&g_waT[(cc + 0) * CCH + c0];
        float4 w1 = *(const float4*)&g_waT[(cc + 1) * CCH + c0];
        float4 w2 = *(const float4*)&g_waT[(cc + 2) * CCH + c0];
        float4 w3 = *(const float4*)&g_waT[(cc + 3) * CCH + c0];
        #pragma unroll
        for (int i = 0; i < 8; i++) {
            float4 a = *(const float4*)&avs[(n0 + i) * CCH + cc];
            acc[i][0] += a.x * w0.x + a.y * w1.x + a.z * w2.x + a.w * w3.x;
            acc[i][1] += a.x * w0.y + a.y * w1.y + a.z * w2.y + a.w * w3.y;
            acc[i][2] += a.x * w0.z + a.y * w1.z + a.z * w2.z + a.w * w3.z;
            acc[i][3] += a.x * w0.w + a.y * w1.w + a.z * w2.w + a.w * w3.w;
        }
    }
    #pragma unroll
    for (int k = 0; k < 4; k++) {
        float b = ba[c0 + k];
        float cs = 0.f, cq2 = 0.f;
        #pragma unroll
        for (int i = 0; i < 8; i++) {
            float yv = acc[i][k] + b;
            g_y[(size_t)(c0 + k) * NPOS + nbase + n0 + i] = yv;
            cs += yv; cq2 += yv * yv;
        }
        atomicAdd(&ssum[c0 + k], cs);
        atomicAdd(&ssq[c0 + k], cq2);
    }
    __syncthreads();
    if (tid < CCH) {
        atomicAdd(&g_sum[tid], ssum[tid]);
        atomicAdd(&g_sq[tid],  ssq[tid]);
    }
}

// ---------------- kernel: BN (from global sums) + ReLU + residual ----------------
__global__ void k_final(const float* __restrict__ x,
                        const float* __restrict__ bnw, const float* __restrict__ bnb,
                        float* __restrict__ out) {
    const int c = blockIdx.y;
    const int n = blockIdx.x * 256 + threadIdx.x;
    if (n >= NPOS) return;
    const float inv = 1.f / (float)NPOS;
    float mean = g_sum[c] * inv;
    float var = g_sq[c] * inv - mean * mean;
    float rstd = rsqrtf(var + 1e-5f);
    size_t idx = (size_t)c * NPOS + n;
    float yv = g_y[idx];
    float o = (yv - mean) * rstd * bnw[c] + bnb[c];
    out[idx] = fmaxf(o, 0.f) + x[idx];
}

// ---------------- launch ----------------
extern "C" void kernel_launch(void* const* d_in, const int* in_sizes, int n_in,
                              void* d_out, int out_size) {
    const float* x   = (const float*)d_in[0];
    const float* wq  = (const float*)d_in[1];
    const float* bq  = (const float*)d_in[2];
    const float* wk  = (const float*)d_in[3];
    const float* bk  = (const float*)d_in[4];
    const float* wv  = (const float*)d_in[5];
    const float* bv  = (const float*)d_in[6];
    const float* wa  = (const float*)d_in[7];
    const float* ba  = (const float*)d_in[8];
    const float* bnw = (const float*)d_in[9];
    const float* bnb = (const float*)d_in[10];
    float* out = (float*)d_out;

    static int smem_set = 0;
    if (!smem_set) {
        cudaFuncSetAttribute(k_flash_mma, cudaFuncAttributeMaxDynamicSharedMemorySize,
                             FLASH_SMEM);
        smem_set = 1;
    }

    k_transpose_w<<<64, 256>>>(wa);
    k_proj_qk<<<250, 256>>>(x, wq, bq, wk, bk);
    k_proj_v<<<dim3(125, 4), 256>>>(x, wv, bv);
    k_flash_mma<<<dim3(QT, NSPLIT), 256, FLASH_SMEM>>>();
    k_ygemm<<<NPOS / 64, 256>>>(ba);
    k_final<<<dim3(32, CCH), 256>>>(x, bnw, bnb, out);
}

// round 13
// speedup vs baseline: 2.7115x; 1.1373x over previous
#include <cuda_runtime.h>
#include <cuda_fp16.h>
#include <cstdint>

// ---------------- problem constants ----------------
#define NPOS   8000
#define CCH    128
#define CQ     16
#define NSPLIT 5
#define JT_PER 25        // 125 j-tiles / 5 splits
#define QT     125       // q tiles of 64

#define QKPITCH 24       // Q/K smem pitch (halfs) -> 48B rows, ldsm conflict-free
#define VPITCH  72       // V smem pitch (halfs) -> 144B rows, conflict-free
#define PPITCH  72       // P smem pitch (halfs)

// smem byte offsets (triple-buffered K/V, double-buffered P)
#define OFF_Q  0                    // half [64][24]           3072 B
#define KBUF   3072
#define OFF_K  3072                 // half [3][64][24]        9216 B
#define VBUF   18432
#define OFF_V  12288                // half [3][128][72]      55296 B
#define PBUF   9216
#define OFF_P  67584                // half [2][64][72]       18432 B
#define OFF_L  86016                // float [64]               256 B
#define FLASH_SMEM 86272

// ---------------- device scratch ----------------
__device__ __half g_q[NPOS * CQ];            // [n][d], fp16
__device__ __half g_k[NPOS * CQ];            // [n][d], fp16
__device__ __half g_v[(size_t)CCH * NPOS];   // [c][n], fp16
__device__ float  g_waT[CCH * CCH];
__device__ float  g_pacc[(size_t)NSPLIT * NPOS * CCH];
__device__ float  g_pl[NSPLIT * NPOS];
__device__ float  g_y[(size_t)CCH * NPOS];
__device__ float  g_sum[CCH], g_sq[CCH];

// ---------------- helpers ----------------
__device__ __forceinline__ uint32_t smem_u32(const void* p) {
    uint32_t a;
    asm("{ .reg .u64 t; cvta.to.shared.u64 t, %1; cvt.u32.u64 %0, t; }" : "=r"(a) : "l"(p));
    return a;
}
__device__ __forceinline__ void mma_f16(float d[4],
                                        uint32_t a0, uint32_t a1, uint32_t a2, uint32_t a3,
                                        uint32_t b0, uint32_t b1) {
    asm volatile("mma.sync.aligned.m16n8k16.row.col.f32.f16.f16.f32 "
                 "{%0,%1,%2,%3}, {%4,%5,%6,%7}, {%8,%9}, {%0,%1,%2,%3};"
                 : "+f"(d[0]), "+f"(d[1]), "+f"(d[2]), "+f"(d[3])
                 : "r"(a0), "r"(a1), "r"(a2), "r"(a3), "r"(b0), "r"(b1));
}
__device__ __forceinline__ void ldsm4(uint32_t r[4], uint32_t addr) {
    asm volatile("ldmatrix.sync.aligned.m8n8.x4.shared.b16 {%0,%1,%2,%3}, [%4];"
                 : "=r"(r[0]), "=r"(r[1]), "=r"(r[2]), "=r"(r[3]) : "r"(addr));
}
#define CPA16(dst, src) \
    asm volatile("cp.async.cg.shared.global [%0], [%1], 16;" :: "r"(dst), "l"(src))
#define CP_COMMIT() asm volatile("cp.async.commit_group;" ::: "memory")
#define CP_WAIT1()  asm volatile("cp.async.wait_group 1;" ::: "memory")
#define CP_WAIT0()  asm volatile("cp.async.wait_group 0;" ::: "memory")

// ---------------- kernel: fused preprocessing ----------------
// blocks 0..63: transpose wa (+zero stats); 64..313: q/k proj; 314..813: v proj
__global__ void __launch_bounds__(256) k_pre(const float* __restrict__ x,
                                             const float* __restrict__ wq,
                                             const float* __restrict__ bq,
                                             const float* __restrict__ wk,
                                             const float* __restrict__ bk,
                                             const float* __restrict__ wv,
                                             const float* __restrict__ bv,
                                             const float* __restrict__ wa) {
    __shared__ float swT[CCH * 32];   // 16 KB, reused by both proj paths
    __shared__ float sb[32];
    const int b = blockIdx.x;
    const int tid = threadIdx.x;

    if (b < 64) {
        int i = b * 256 + tid;
        if (i < CCH) { g_sum[i] = 0.f; g_sq[i] = 0.f; }
        int r = i >> 7, c = i & 127;
        g_waT[c * CCH + r] = wa[r * CCH + c];
        return;
    }

    if (b < 314) {
        // ---- q/k projection ----
        for (int i = tid; i < 16 * CCH; i += 256) {
            int d = i >> 7, cc = i & 127;
            swT[cc * 32 + d]      = wq[i];
            swT[cc * 32 + 16 + d] = wk[i];
        }
        if (tid < 16) sb[tid] = bq[tid];
        else if (tid < 32) sb[tid] = bk[tid - 16];
        __syncthreads();

        const int n  = (b - 64) * 32 + (tid & 31);
        const int og = tid >> 5;
        float a0 = sb[og * 4 + 0], a1 = sb[og * 4 + 1];
        float a2 = sb[og * 4 + 2], a3 = sb[og * 4 + 3];
        #pragma unroll 4
        for (int cc = 0; cc < CCH; cc++) {
            float xv = x[cc * NPOS + n];
            float4 w = *(const float4*)&swT[cc * 32 + og * 4];
            a0 += w.x * xv; a1 += w.y * xv; a2 += w.z * xv; a3 += w.w * xv;
        }
        __half* o = (og < 4) ? g_q : g_k;
        int d0 = (og < 4) ? og * 4 : (og - 4) * 4;
        o[n * CQ + d0 + 0] = __float2half_rn(a0);
        o[n * CQ + d0 + 1] = __float2half_rn(a1);
        o[n * CQ + d0 + 2] = __float2half_rn(a2);
        o[n * CQ + d0 + 3] = __float2half_rn(a3);
        return;
    }

    // ---- v projection ----
    {
        const int vb = b - 314;                 // 0..499
        const int nb = (vb % 125) * 64;
        const int cb = (vb / 125) * 32;
        for (int i = tid; i < 32 * CCH; i += 256) {
            int r = i >> 7, c = i & 127;
            swT[i] = wv[(cb + r) * CCH + c];
        }
        __syncthreads();
        const int n = nb + (tid & 63);
        const int c0 = (tid >> 6) * 8;
        float acc[8];
        #pragma unroll
        for (int i = 0; i < 8; i++) acc[i] = bv[cb + c0 + i];
        #pragma unroll 4
        for (int cc4 = 0; cc4 < 32; cc4++) {
            float x0 = x[(cc4 * 4 + 0) * NPOS + n];
            float x1 = x[(cc4 * 4 + 1) * NPOS + n];
            float x2 = x[(cc4 * 4 + 2) * NPOS + n];
            float x3 = x[(cc4 * 4 + 3) * NPOS + n];
            #pragma unroll
            for (int i = 0; i < 8; i++) {
                float4 w = *(const float4*)&swT[(c0 + i) * CCH + cc4 * 4];
                acc[i] += w.x * x0 + w.y * x1 + w.z * x2 + w.w * x3;
            }
        }
        #pragma unroll
        for (int i = 0; i < 8; i++)
            g_v[(size_t)(cb + c0 + i) * NPOS + n] = __float2half_rn(acc[i]);
    }
}

// ---------------- kernel: flash attention, all-fp16 MMA, 2 barriers/iter ----------------
__global__ void __launch_bounds__(256, 2) k_flash_mma() {
    extern __shared__ char smc[];
    float* sL = (float*)(smc + OFF_L);
    const uint32_t smb = smem_u32(smc);

    const int tid  = threadIdx.x;
    const int wid  = tid >> 5;
    const int lane = tid & 31;
    const int g    = lane >> 2;     // groupID (0..7)
    const int tq   = lane & 3;      // threadID_in_group

    const int qt = blockIdx.x, sp = blockIdx.y;
    const int qbase = qt * 64;
    const int jt0 = sp * JT_PER;

    // MMA1/softmax mapping: 4 q-blocks x 2 j-halves
    const int qb = (wid >> 1) * 16;
    const int jh = (wid & 1) * 32;
    // MMA2 mapping: 2 q-halves x 4 c-quarters
    const int qh2 = (wid >> 2) * 32;
    const int cq  = (wid & 3) * 32;

    if (tid < 64) sL[tid] = 0.f;

    // load Q tile: 64 rows x 16 halfs
    if (tid < 128) {
        int row = tid >> 1, seg = tid & 1;
        *(uint4*)(smc + OFF_Q + row * (QKPITCH * 2) + seg * 16) =
            *(const uint4*)&g_q[(qbase + row) * CQ + seg * 8];
    }

    // prefetch pointers
    const int krow = tid >> 1, kseg = tid & 1;     // tid<128 only
    const int vc0 = tid >> 3, vj16 = tid & 7;
    const __half* srcK = &g_k[(jt0 * 64 + krow) * CQ + kseg * 8];
    const __half* srcV = &g_v[(size_t)vc0 * NPOS + jt0 * 64 + vj16 * 8];
    const uint32_t dstK0 = smb + OFF_K + (uint32_t)(krow * QKPITCH + kseg * 8) * 2;
    const uint32_t dstV0 = smb + OFF_V + (uint32_t)(vc0 * VPITCH + vj16 * 8) * 2;

    auto prefetch = [&](int bufi) {
        if (tid < 128) CPA16(dstK0 + bufi * KBUF, srcK);
        uint32_t dv = dstV0 + bufi * VBUF;
        #pragma unroll
        for (int i = 0; i < 4; i++)      // 4 x (32 c-rows)
            CPA16(dv + i * (32 * VPITCH * 2), srcV + (size_t)i * 32 * NPOS);
        CP_COMMIT();
        srcK += 64 * CQ;
        srcV += 64;
    };

    float D[2][4][4];
    #pragma unroll
    for (int qi = 0; qi < 2; qi++)
        #pragma unroll
        for (int nt = 0; nt < 4; nt++)
            #pragma unroll
            for (int k = 0; k < 4; k++) D[qi][nt][k] = 0.f;
    float l0 = 0.f, l1 = 0.f;

    prefetch(0);   // tile 0 -> buffer 0
    __syncthreads();   // Q visible before hoisted ldmatrix

    // hoisted Q A-fragment (loop-invariant)
    uint32_t qa[4];
    ldsm4(qa, smb + OFF_Q + (uint32_t)((qb + (lane & 15)) * QKPITCH + (lane >> 4) * 8) * 2);

    // ldsm per-thread byte offsets
    const uint32_t bK = (uint32_t)(((lane & 7) + ((lane >> 4) * 8)) * QKPITCH
                                   + ((lane >> 3) & 1) * 8) * 2;
    const uint32_t aoff = (uint32_t)((lane & 15) * PPITCH + (lane >> 4) * 8) * 2;
    const uint32_t boff = (uint32_t)(((lane & 7) + ((lane >> 4) * 8)) * VPITCH
                                     + ((lane >> 3) & 1) * 8) * 2;

    int cur3 = 0;        // tile it lives in buffer it%3
    int curp = 0;        // P buffer it%2
    for (int it = 0; it < JT_PER; it++) {
        int nxt3 = (cur3 == 2) ? 0 : cur3 + 1;
        if (it + 1 < JT_PER) { prefetch(nxt3); CP_WAIT1(); }
        else                 { CP_WAIT0(); }
        __syncthreads();   // sync1: K/V(cur3) ready; everyone finished iter it-1
                           // (also fences WAR for prefetch into nxt3: its last
                           // readers were iter it-2, done before sync1(it-1))

        // ---- MMA1 (fp16 k16): S[16q x 32j] per warp ----
        float S[4][4];
        #pragma unroll
        for (int nt = 0; nt < 4; nt++)
            #pragma unroll
            for (int k = 0; k < 4; k++) S[nt][k] = 0.f;
        {
            const uint32_t kbase = smb + OFF_K + cur3 * KBUF;
            uint32_t kb0[4], kb1[4];
            ldsm4(kb0, kbase + (uint32_t)(jh * QKPITCH) * 2 + bK);
            ldsm4(kb1, kbase + (uint32_t)((jh + 16) * QKPITCH) * 2 + bK);
            mma_f16(S[0], qa[0], qa[1], qa[2], qa[3], kb0[0], kb0[1]);
            mma_f16(S[1], qa[0], qa[1], qa[2], qa[3], kb0[2], kb0[3]);
            mma_f16(S[2], qa[0], qa[1], qa[2], qa[3], kb1[0], kb1[1]);
            mma_f16(S[3], qa[0], qa[1], qa[2], qa[3], kb1[2], kb1[3]);
        }

        // ---- softmax (no max-subtraction) + fp16 pack + store P[curp] ----
        {
            char* pB = smc + OFF_P + curp * PBUF;
            #pragma unroll
            for (int nt = 0; nt < 4; nt++) {
                float p0 = __expf(S[nt][0]);
                float p1 = __expf(S[nt][1]);
                float p2 = __expf(S[nt][2]);
                float p3 = __expf(S[nt][3]);
                l0 += p0 + p1;
                l1 += p2 + p3;
                int col = jh + nt * 8 + 2 * tq;
                *(__half2*)(pB + ((qb + g) * PPITCH + col) * 2) =
                    __floats2half2_rn(p0, p1);
                *(__half2*)(pB + ((qb + g + 8) * PPITCH + col) * 2) =
                    __floats2half2_rn(p2, p3);
            }
        }
        // sync2 (split): MMA2 of warps 0-3 reads only P rows 0-31 (written by
        // warps 0-3); warps 4-7 likewise rows 32-63.
        if (wid < 4) asm volatile("bar.sync 3, 128;" ::: "memory");
        else         asm volatile("bar.sync 4, 128;" ::: "memory");

        // ---- MMA2 (fp16 k16): D[32q x 32c] per warp ----
        {
            const uint32_t pbase = smb + OFF_P + curp * PBUF;
            const uint32_t vbase = smb + OFF_V + cur3 * VBUF;
            #pragma unroll
            for (int kc = 0; kc < 4; kc++) {
                uint32_t pa0[4], pa1[4], vb0[4], vb1[4];
                ldsm4(pa0, pbase + (uint32_t)(qh2 * PPITCH) * 2 + kc * 32 + aoff);
                ldsm4(pa1, pbase + (uint32_t)((qh2 + 16) * PPITCH) * 2 + kc * 32 + aoff);
                ldsm4(vb0, vbase + (uint32_t)(cq * VPITCH) * 2 + kc * 32 + boff);
                ldsm4(vb1, vbase + (uint32_t)((cq + 16) * VPITCH) * 2 + kc * 32 + boff);
                mma_f16(D[0][0], pa0[0], pa0[1], pa0[2], pa0[3], vb0[0], vb0[1]);
                mma_f16(D[0][1], pa0[0], pa0[1], pa0[2], pa0[3], vb0[2], vb0[3]);
                mma_f16(D[0][2], pa0[0], pa0[1], pa0[2], pa0[3], vb1[0], vb1[1]);
                mma_f16(D[0][3], pa0[0], pa0[1], pa0[2], pa0[3], vb1[2], vb1[3]);
                mma_f16(D[1][0], pa1[0], pa1[1], pa1[2], pa1[3], vb0[0], vb0[1]);
                mma_f16(D[1][1], pa1[0], pa1[1], pa1[2], pa1[3], vb0[2], vb0[3]);
                mma_f16(D[1][2], pa1[0], pa1[1], pa1[2], pa1[3], vb1[0], vb1[1]);
                mma_f16(D[1][3], pa1[0], pa1[1], pa1[2], pa1[3], vb1[2], vb1[3]);
            }
        }
        // no end-of-iter barrier: triple-buffered K/V + double-buffered P
        // make next iteration's writes hazard-free; sync1 bounds warp skew.
        cur3 = nxt3;
        curp ^= 1;
    }

    // ---- l reduction ----
    l0 += __shfl_xor_sync(0xffffffffu, l0, 1);
    l0 += __shfl_xor_sync(0xffffffffu, l0, 2);
    l1 += __shfl_xor_sync(0xffffffffu, l1, 1);
    l1 += __shfl_xor_sync(0xffffffffu, l1, 2);
    if (tq == 0) {
        atomicAdd(&sL[qb + g], l0);
        atomicAdd(&sL[qb + g + 8], l1);
    }
    __syncthreads();
    if (tid < 64)
        g_pl[sp * NPOS + qbase + tid] = sL[tid];

    // ---- write D partials ----
    #pragma unroll
    for (int qi = 0; qi < 2; qi++) {
        #pragma unroll
        for (int nt = 0; nt < 4; nt++) {
            int col = cq + nt * 8 + 2 * tq;
            int r0 = qbase + qh2 + qi * 16 + g;
            *(float2*)&g_pacc[((size_t)sp * NPOS + r0) * CCH + col] =
                make_float2(D[qi][nt][0], D[qi][nt][1]);
            *(float2*)&g_pacc[((size_t)sp * NPOS + r0 + 8) * CCH + col] =
                make_float2(D[qi][nt][2], D[qi][nt][3]);
        }
    }
}

// ---- kernel: fused combine + output projection + BN stat partials ----------
__global__ void __launch_bounds__(256) k_ygemm(const float* __restrict__ ba) {
    __shared__ float avs[64 * CCH];     // 32 KB
    __shared__ float sLr[64];
    __shared__ float ssum[CCH], ssq[CCH];
    const int tid = threadIdx.x;
    const int nbase = blockIdx.x * 64;

    if (tid < 64) {
        float L = 0.f;
        #pragma unroll
        for (int s = 0; s < NSPLIT; s++) L += g_pl[s * NPOS + nbase + tid];
        sLr[tid] = 1.f / L;
    }
    if (tid < CCH) { ssum[tid] = 0.f; ssq[tid] = 0.f; }
    __syncthreads();

    // combine splits directly into the smem tile
    for (int t = tid; t < 64 * (CCH / 4); t += 256) {
        int n = t >> 5;
        int c4 = (t & 31) << 2;
        float4 a = make_float4(0.f, 0.f, 0.f, 0.f);
        #pragma unroll
        for (int s = 0; s < NSPLIT; s++) {
            float4 p = *(const float4*)&g_pacc[((size_t)s * NPOS + nbase + n) * CCH + c4];
            a.x += p.x; a.y += p.y; a.z += p.z; a.w += p.w;
        }
        float r = sLr[n];
        a.x *= r; a.y *= r; a.z *= r; a.w *= r;
        *(float4*)&avs[n * CCH + c4] = a;
    }
    __syncthreads();

    const int c0 = (tid & 31) * 4;
    const int n0 = (tid >> 5) * 8;
    float acc[8][4];
    #pragma unroll
    for (int i = 0; i < 8; i++)
        #pragma unroll
        for (int k = 0; k < 4; k++) acc[i][k] = 0.f;
    #pragma unroll 2
    for (int cc = 0; cc < CCH; cc += 4) {
        float4 w0 = *(const float4*)&g_waT[(cc + 0) * CCH + c0];
        float4 w1 = *(const float4*)&g_waT[(cc + 1) * CCH + c0];
        float4 w2 = *(const float4*)&g_waT[(cc + 2) * CCH + c0];
        float4 w3 = *(const float4*)&g_waT[(cc + 3) * CCH + c0];
        #pragma unroll
        for (int i = 0; i < 8; i++) {
            float4 a = *(const float4*)&avs[(n0 + i) * CCH + cc];
            acc[i][0] += a.x * w0.x + a.y * w1.x + a.z * w2.x + a.w * w3.x;
            acc[i][1] += a.x * w0.y + a.y * w1.y + a.z * w2.y + a.w * w3.y;
            acc[i][2] += a.x * w0.z + a.y * w1.z + a.z * w2.z + a.w * w3.z;
            acc[i][3] += a.x * w0.w + a.y * w1.w + a.z * w2.w + a.w * w3.w;
        }
    }
    #pragma unroll
    for (int k = 0; k < 4; k++) {
        float b = ba[c0 + k];
        float cs = 0.f, cq2 = 0.f;
        #pragma unroll
        for (int i = 0; i < 8; i++) {
            float yv = acc[i][k] + b;
            g_y[(size_t)(c0 + k) * NPOS + nbase + n0 + i] = yv;
            cs += yv; cq2 += yv * yv;
        }
        atomicAdd(&ssum[c0 + k], cs);
        atomicAdd(&ssq[c0 + k], cq2);
    }
    __syncthreads();
    if (tid < CCH) {
        atomicAdd(&g_sum[tid], ssum[tid]);
        atomicAdd(&g_sq[tid],  ssq[tid]);
    }
}

// ---------------- kernel: BN (from global sums) + ReLU + residual ----------------
__global__ void k_final(const float* __restrict__ x,
                        const float* __restrict__ bnw, const float* __restrict__ bnb,
                        float* __restrict__ out) {
    const int c = blockIdx.y;
    const int n = blockIdx.x * 256 + threadIdx.x;
    if (n >= NPOS) return;
    const float inv = 1.f / (float)NPOS;
    float mean = g_sum[c] * inv;
    float var = g_sq[c] * inv - mean * mean;
    float rstd = rsqrtf(var + 1e-5f);
    size_t idx = (size_t)c * NPOS + n;
    float yv = g_y[idx];
    float o = (yv - mean) * rstd * bnw[c] + bnb[c];
    out[idx] = fmaxf(o, 0.f) + x[idx];
}

// ---------------- launch ----------------
extern "C" void kernel_launch(void* const* d_in, const int* in_sizes, int n_in,
                              void* d_out, int out_size) {
    const float* x   = (const float*)d_in[0];
    const float* wq  = (const float*)d_in[1];
    const float* bq  = (const float*)d_in[2];
    const float* wk  = (const float*)d_in[3];
    const float* bk  = (const float*)d_in[4];
    const float* wv  = (const float*)d_in[5];
    const float* bv  = (const float*)d_in[6];
    const float* wa  = (const float*)d_in[7];
    const float* ba  = (const float*)d_in[8];
    const float* bnw = (const float*)d_in[9];
    const float* bnb = (const float*)d_in[10];
    float* out = (float*)d_out;

    static int smem_set = 0;
    if (!smem_set) {
        cudaFuncSetAttribute(k_flash_mma, cudaFuncAttributeMaxDynamicSharedMemorySize,
                             FLASH_SMEM);
        smem_set = 1;
    }

    k_pre<<<814, 256>>>(x, wq, bq, wk, bk, wv, bv, wa);
    k_flash_mma<<<dim3(QT, NSPLIT), 256, FLASH_SMEM>>>();
    k_ygemm<<<NPOS / 64, 256>>>(ba);
    k_final<<<dim3(32, CCH), 256>>>(x, bnw, bnb, out);
}

// round 16
// speedup vs baseline: 2.8986x; 1.0690x over previous
#include <cuda_runtime.h>
#include <cuda_fp16.h>
#include <cstdint>

// ---------------- problem constants ----------------
#define NPOS   8000
#define CCH    128
#define CQ     16
#define NSPLIT 2         // splits of 63 / 62 j-tiles -> grid 250 = ONE wave
#define QT     125       // q tiles of 64

#define QKPITCH 24       // Q/K smem pitch (halfs) -> 48B rows, ldsm conflict-free
#define VPITCH  72       // V smem pitch (halfs) -> 144B rows, conflict-free
#define PPITCH  72       // P smem pitch (halfs)

// smem byte offsets (triple-buffered K/V, double-buffered P)
#define OFF_Q  0                    // half [64][24]           3072 B
#define KBUF   3072
#define OFF_K  3072                 // half [3][64][24]        9216 B
#define VBUF   18432
#define OFF_V  12288                // half [3][128][72]      55296 B
#define PBUF   9216
#define OFF_P  67584                // half [2][64][72]       18432 B
#define OFF_L  86016                // float [64]               256 B
#define FLASH_SMEM 86272

// ---------------- device scratch ----------------
__device__ __half g_q[NPOS * CQ];            // [n][d], fp16
__device__ __half g_k[NPOS * CQ];            // [n][d], fp16
__device__ __half g_v[(size_t)CCH * NPOS];   // [c][n], fp16
__device__ float  g_waT[CCH * CCH];
__device__ float  g_pacc[(size_t)NSPLIT * NPOS * CCH];
__device__ float  g_pl[NSPLIT * NPOS];
__device__ float  g_y[(size_t)CCH * NPOS];
__device__ float  g_sum[CCH], g_sq[CCH];

// ---------------- helpers ----------------
__device__ __forceinline__ uint32_t smem_u32(const void* p) {
    uint32_t a;
    asm("{ .reg .u64 t; cvta.to.shared.u64 t, %1; cvt.u32.u64 %0, t; }" : "=r"(a) : "l"(p));
    return a;
}
__device__ __forceinline__ void mma_f16(float d[4],
                                        uint32_t a0, uint32_t a1, uint32_t a2, uint32_t a3,
                                        uint32_t b0, uint32_t b1) {
    asm volatile("mma.sync.aligned.m16n8k16.row.col.f32.f16.f16.f32 "
                 "{%0,%1,%2,%3}, {%4,%5,%6,%7}, {%8,%9}, {%0,%1,%2,%3};"
                 : "+f"(d[0]), "+f"(d[1]), "+f"(d[2]), "+f"(d[3])
                 : "r"(a0), "r"(a1), "r"(a2), "r"(a3), "r"(b0), "r"(b1));
}
__device__ __forceinline__ void ldsm4(uint32_t r[4], uint32_t addr) {
    asm volatile("ldmatrix.sync.aligned.m8n8.x4.shared.b16 {%0,%1,%2,%3}, [%4];"
                 : "=r"(r[0]), "=r"(r[1]), "=r"(r[2]), "=r"(r[3]) : "r"(addr));
}
#define CPA16(dst, src) \
    asm volatile("cp.async.cg.shared.global [%0], [%1], 16;" :: "r"(dst), "l"(src))
#define CP_COMMIT() asm volatile("cp.async.commit_group;" ::: "memory")
#define CP_WAIT1()  asm volatile("cp.async.wait_group 1;" ::: "memory")
#define CP_WAIT0()  asm volatile("cp.async.wait_group 0;" ::: "memory")

// ---------------- kernel: fused preprocessing ----------------
// blocks 0..63: transpose wa (+zero stats); 64..313: q/k proj; 314..813: v proj
__global__ void __launch_bounds__(256) k_pre(const float* __restrict__ x,
                                             const float* __restrict__ wq,
                                             const float* __restrict__ bq,
                                             const float* __restrict__ wk,
                                             const float* __restrict__ bk,
                                             const float* __restrict__ wv,
                                             const float* __restrict__ bv,
                                             const float* __restrict__ wa) {
    __shared__ float swT[CCH * 32];   // 16 KB, reused by both proj paths
    __shared__ float sb[32];
    const int b = blockIdx.x;
    const int tid = threadIdx.x;

    if (b < 64) {
        int i = b * 256 + tid;
        if (i < CCH) { g_sum[i] = 0.f; g_sq[i] = 0.f; }
        int r = i >> 7, c = i & 127;
        g_waT[c * CCH + r] = wa[r * CCH + c];
        return;
    }

    if (b < 314) {
        // ---- q/k projection ----
        for (int i = tid; i < 16 * CCH; i += 256) {
            int d = i >> 7, cc = i & 127;
            swT[cc * 32 + d]      = wq[i];
            swT[cc * 32 + 16 + d] = wk[i];
        }
        if (tid < 16) sb[tid] = bq[tid];
        else if (tid < 32) sb[tid] = bk[tid - 16];
        __syncthreads();

        const int n  = (b - 64) * 32 + (tid & 31);
        const int og = tid >> 5;
        float a0 = sb[og * 4 + 0], a1 = sb[og * 4 + 1];
        float a2 = sb[og * 4 + 2], a3 = sb[og * 4 + 3];
        #pragma unroll 4
        for (int cc = 0; cc < CCH; cc++) {
            float xv = x[cc * NPOS + n];
            float4 w = *(const float4*)&swT[cc * 32 + og * 4];
            a0 += w.x * xv; a1 += w.y * xv; a2 += w.z * xv; a3 += w.w * xv;
        }
        __half* o = (og < 4) ? g_q : g_k;
        int d0 = (og < 4) ? og * 4 : (og - 4) * 4;
        o[n * CQ + d0 + 0] = __float2half_rn(a0);
        o[n * CQ + d0 + 1] = __float2half_rn(a1);
        o[n * CQ + d0 + 2] = __float2half_rn(a2);
        o[n * CQ + d0 + 3] = __float2half_rn(a3);
        return;
    }

    // ---- v projection ----
    {
        const int vb = b - 314;                 // 0..499
        const int nb = (vb % 125) * 64;
        const int cb = (vb / 125) * 32;
        for (int i = tid; i < 32 * CCH; i += 256) {
            int r = i >> 7, c = i & 127;
            swT[i] = wv[(cb + r) * CCH + c];
        }
        __syncthreads();
        const int n = nb + (tid & 63);
        const int c0 = (tid >> 6) * 8;
        float acc[8];
        #pragma unroll
        for (int i = 0; i < 8; i++) acc[i] = bv[cb + c0 + i];
        #pragma unroll 4
        for (int cc4 = 0; cc4 < 32; cc4++) {
            float x0 = x[(cc4 * 4 + 0) * NPOS + n];
            float x1 = x[(cc4 * 4 + 1) * NPOS + n];
            float x2 = x[(cc4 * 4 + 2) * NPOS + n];
            float x3 = x[(cc4 * 4 + 3) * NPOS + n];
            #pragma unroll
            for (int i = 0; i < 8; i++) {
                float4 w = *(const float4*)&swT[(c0 + i) * CCH + cc4 * 4];
                acc[i] += w.x * x0 + w.y * x1 + w.z * x2 + w.w * x3;
            }
        }
        #pragma unroll
        for (int i = 0; i < 8; i++)
            g_v[(size_t)(cb + c0 + i) * NPOS + n] = __float2half_rn(acc[i]);
    }
}

// ---------------- kernel: flash attention, all-fp16 MMA, 2 barriers/iter ----------------
__global__ void __launch_bounds__(256, 2) k_flash_mma() {
    extern __shared__ char smc[];
    float* sL = (float*)(smc + OFF_L);
    const uint32_t smb = smem_u32(smc);

    const int tid  = threadIdx.x;
    const int wid  = tid >> 5;
    const int lane = tid & 31;
    const int g    = lane >> 2;     // groupID (0..7)
    const int tq   = lane & 3;      // threadID_in_group

    const int qt = blockIdx.x, sp = blockIdx.y;
    const int qbase = qt * 64;
    const int jt0   = sp ? 63 : 0;
    const int niter = sp ? 62 : 63;

    // MMA1/softmax mapping: 4 q-blocks x 2 j-halves
    const int qb = (wid >> 1) * 16;
    const int jh = (wid & 1) * 32;
    // MMA2 mapping: 2 q-halves x 4 c-quarters
    const int qh2 = (wid >> 2) * 32;
    const int cq  = (wid & 3) * 32;

    if (tid < 64) sL[tid] = 0.f;

    // load Q tile: 64 rows x 16 halfs
    if (tid < 128) {
        int row = tid >> 1, seg = tid & 1;
        *(uint4*)(smc + OFF_Q + row * (QKPITCH * 2) + seg * 16) =
            *(const uint4*)&g_q[(qbase + row) * CQ + seg * 8];
    }

    // prefetch pointers
    const int krow = tid >> 1, kseg = tid & 1;     // tid<128 only
    const int vc0 = tid >> 3, vj16 = tid & 7;
    const __half* srcK = &g_k[(jt0 * 64 + krow) * CQ + kseg * 8];
    const __half* srcV = &g_v[(size_t)vc0 * NPOS + jt0 * 64 + vj16 * 8];
    const uint32_t dstK0 = smb + OFF_K + (uint32_t)(krow * QKPITCH + kseg * 8) * 2;
    const uint32_t dstV0 = smb + OFF_V + (uint32_t)(vc0 * VPITCH + vj16 * 8) * 2;

    auto prefetch = [&](int bufi) {
        if (tid < 128) CPA16(dstK0 + bufi * KBUF, srcK);
        uint32_t dv = dstV0 + bufi * VBUF;
        #pragma unroll
        for (int i = 0; i < 4; i++)      // 4 x (32 c-rows)
            CPA16(dv + i * (32 * VPITCH * 2), srcV + (size_t)i * 32 * NPOS);
        CP_COMMIT();
        srcK += 64 * CQ;
        srcV += 64;
    };

    float D[2][4][4];
    #pragma unroll
    for (int qi = 0; qi < 2; qi++)
        #pragma unroll
        for (int nt = 0; nt < 4; nt++)
            #pragma unroll
            for (int k = 0; k < 4; k++) D[qi][nt][k] = 0.f;
    float l0 = 0.f, l1 = 0.f;

    prefetch(0);   // tile 0 -> buffer 0
    __syncthreads();   // Q visible before hoisted ldmatrix

    // hoisted Q A-fragment (loop-invariant)
    uint32_t qa[4];
    ldsm4(qa, smb + OFF_Q + (uint32_t)((qb + (lane & 15)) * QKPITCH + (lane >> 4) * 8) * 2);

    // ldsm per-thread byte offsets
    const uint32_t bK = (uint32_t)(((lane & 7) + ((lane >> 4) * 8)) * QKPITCH
                                   + ((lane >> 3) & 1) * 8) * 2;
    const uint32_t aoff = (uint32_t)((lane & 15) * PPITCH + (lane >> 4) * 8) * 2;
    const uint32_t boff = (uint32_t)(((lane & 7) + ((lane >> 4) * 8)) * VPITCH
                                     + ((lane >> 3) & 1) * 8) * 2;

    int cur3 = 0;        // tile it lives in buffer it%3
    int curp = 0;        // P buffer it%2
    for (int it = 0; it < niter; it++) {
        int nxt3 = (cur3 == 2) ? 0 : cur3 + 1;
        if (it + 1 < niter) { prefetch(nxt3); CP_WAIT1(); }
        else                { CP_WAIT0(); }
        __syncthreads();   // sync1: K/V(cur3) ready; everyone finished iter it-1
                           // (also fences WAR for prefetch into nxt3: its last
                           // readers were iter it-2, done before sync1(it-1))

        // ---- MMA1 (fp16 k16): S[16q x 32j] per warp ----
        float S[4][4];
        #pragma unroll
        for (int nt = 0; nt < 4; nt++)
            #pragma unroll
            for (int k = 0; k < 4; k++) S[nt][k] = 0.f;
        {
            const uint32_t kbase = smb + OFF_K + cur3 * KBUF;
            uint32_t kb0[4], kb1[4];
            ldsm4(kb0, kbase + (uint32_t)(jh * QKPITCH) * 2 + bK);
            ldsm4(kb1, kbase + (uint32_t)((jh + 16) * QKPITCH) * 2 + bK);
            mma_f16(S[0], qa[0], qa[1], qa[2], qa[3], kb0[0], kb0[1]);
            mma_f16(S[1], qa[0], qa[1], qa[2], qa[3], kb0[2], kb0[3]);
            mma_f16(S[2], qa[0], qa[1], qa[2], qa[3], kb1[0], kb1[1]);
            mma_f16(S[3], qa[0], qa[1], qa[2], qa[3], kb1[2], kb1[3]);
        }

        // ---- softmax (no max-subtraction) + fp16 pack + store P[curp] ----
        {
            char* pB = smc + OFF_P + curp * PBUF;
            #pragma unroll
            for (int nt = 0; nt < 4; nt++) {
                float p0 = __expf(S[nt][0]);
                float p1 = __expf(S[nt][1]);
                float p2 = __expf(S[nt][2]);
                float p3 = __expf(S[nt][3]);
                l0 += p0 + p1;
                l1 += p2 + p3;
                int col = jh + nt * 8 + 2 * tq;
                *(__half2*)(pB + ((qb + g) * PPITCH + col) * 2) =
                    __floats2half2_rn(p0, p1);
                *(__half2*)(pB + ((qb + g + 8) * PPITCH + col) * 2) =
                    __floats2half2_rn(p2, p3);
            }
        }
        // sync2 (split): MMA2 of warps 0-3 reads only P rows 0-31 (written by
        // warps 0-3); warps 4-7 likewise rows 32-63.
        if (wid < 4) asm volatile("bar.sync 3, 128;" ::: "memory");
        else         asm volatile("bar.sync 4, 128;" ::: "memory");

        // ---- MMA2 (fp16 k16): D[32q x 32c] per warp ----
        {
            const uint32_t pbase = smb + OFF_P + curp * PBUF;
            const uint32_t vbase = smb + OFF_V + cur3 * VBUF;
            #pragma unroll
            for (int kc = 0; kc < 4; kc++) {
                uint32_t pa0[4], pa1[4], vb0[4], vb1[4];
                ldsm4(pa0, pbase + (uint32_t)(qh2 * PPITCH) * 2 + kc * 32 + aoff);
                ldsm4(pa1, pbase + (uint32_t)((qh2 + 16) * PPITCH) * 2 + kc * 32 + aoff);
                ldsm4(vb0, vbase + (uint32_t)(cq * VPITCH) * 2 + kc * 32 + boff);
                ldsm4(vb1, vbase + (uint32_t)((cq + 16) * VPITCH) * 2 + kc * 32 + boff);
                mma_f16(D[0][0], pa0[0], pa0[1], pa0[2], pa0[3], vb0[0], vb0[1]);
                mma_f16(D[0][1], pa0[0], pa0[1], pa0[2], pa0[3], vb0[2], vb0[3]);
                mma_f16(D[0][2], pa0[0], pa0[1], pa0[2], pa0[3], vb1[0], vb1[1]);
                mma_f16(D[0][3], pa0[0], pa0[1], pa0[2], pa0[3], vb1[2], vb1[3]);
                mma_f16(D[1][0], pa1[0], pa1[1], pa1[2], pa1[3], vb0[0], vb0[1]);
                mma_f16(D[1][1], pa1[0], pa1[1], pa1[2], pa1[3], vb0[2], vb0[3]);
                mma_f16(D[1][2], pa1[0], pa1[1], pa1[2], pa1[3], vb1[0], vb1[1]);
                mma_f16(D[1][3], pa1[0], pa1[1], pa1[2], pa1[3], vb1[2], vb1[3]);
            }
        }
        // no end-of-iter barrier: triple-buffered K/V + double-buffered P
        // make next iteration's writes hazard-free; sync1 bounds warp skew.
        cur3 = nxt3;
        curp ^= 1;
    }

    // ---- l reduction ----
    l0 += __shfl_xor_sync(0xffffffffu, l0, 1);
    l0 += __shfl_xor_sync(0xffffffffu, l0, 2);
    l1 += __shfl_xor_sync(0xffffffffu, l1, 1);
    l1 += __shfl_xor_sync(0xffffffffu, l1, 2);
    if (tq == 0) {
        atomicAdd(&sL[qb + g], l0);
        atomicAdd(&sL[qb + g + 8], l1);
    }
    __syncthreads();
    if (tid < 64)
        g_pl[sp * NPOS + qbase + tid] = sL[tid];

    // ---- write D partials ----
    #pragma unroll
    for (int qi = 0; qi < 2; qi++) {
        #pragma unroll
        for (int nt = 0; nt < 4; nt++) {
            int col = cq + nt * 8 + 2 * tq;
            int r0 = qbase + qh2 + qi * 16 + g;
            *(float2*)&g_pacc[((size_t)sp * NPOS + r0) * CCH + col] =
                make_float2(D[qi][nt][0], D[qi][nt][1]);
            *(float2*)&g_pacc[((size_t)sp * NPOS + r0 + 8) * CCH + col] =
                make_float2(D[qi][nt][2], D[qi][nt][3]);
        }
    }
}

// ---- kernel: fused combine + output projection + BN stat partials ----------
// n-tile = 32 -> grid 250 (fills the chip)
__global__ void __launch_bounds__(256) k_ygemm(const float* __restrict__ ba) {
    __shared__ float avs[32 * CCH];     // 16 KB
    __shared__ float sLr[32];
    __shared__ float ssum[CCH], ssq[CCH];
    const int tid = threadIdx.x;
    const int nbase = blockIdx.x * 32;

    if (tid < 32) {
        float L = 0.f;
        #pragma unroll
        for (int s = 0; s < NSPLIT; s++) L += g_pl[s * NPOS + nbase + tid];
        sLr[tid] = 1.f / L;
    }
    if (tid < CCH) { ssum[tid] = 0.f; ssq[tid] = 0.f; }
    __syncthreads();

    // combine splits directly into the smem tile
    for (int t = tid; t < 32 * (CCH / 4); t += 256) {
        int n = t >> 5;
        int c4 = (t & 31) << 2;
        float4 a = make_float4(0.f, 0.f, 0.f, 0.f);
        #pragma unroll
        for (int s = 0; s < NSPLIT; s++) {
            float4 p = *(const float4*)&g_pacc[((size_t)s * NPOS + nbase + n) * CCH + c4];
            a.x += p.x; a.y += p.y; a.z += p.z; a.w += p.w;
        }
        float r = sLr[n];
        a.x *= r; a.y *= r; a.z *= r; a.w *= r;
        *(float4*)&avs[n * CCH + c4] = a;
    }
    __syncthreads();

    const int c0 = (tid & 31) * 4;
    const int n0 = (tid >> 5) * 4;
    float acc[4][4];
    #pragma unroll
    for (int i = 0; i < 4; i++)
        #pragma unroll
        for (int k = 0; k < 4; k++) acc[i][k] = 0.f;
    #pragma unroll 2
    for (int cc = 0; cc < CCH; cc += 4) {
        float4 w0 = *(const float4*)&g_waT[(cc + 0) * CCH + c0];
        float4 w1 = *(const float4*)&g_waT[(cc + 1) * CCH + c0];
        float4 w2 = *(const float4*)&g_waT[(cc + 2) * CCH + c0];
        float4 w3 = *(const float4*)&g_waT[(cc + 3) * CCH + c0];
        #pragma unroll
        for (int i = 0; i < 4; i++) {
            float4 a = *(const float4*)&avs[(n0 + i) * CCH + cc];
            acc[i][0] += a.x * w0.x + a.y * w1.x + a.z * w2.x + a.w * w3.x;
            acc[i][1] += a.x * w0.y + a.y * w1.y + a.z * w2.y + a.w * w3.y;
            acc[i][2] += a.x * w0.z + a.y * w1.z + a.z * w2.z + a.w * w3.z;
            acc[i][3] += a.x * w0.w + a.y * w1.w + a.z * w2.w + a.w * w3.w;
        }
    }
    #pragma unroll
    for (int k = 0; k < 4; k++) {
        float b = ba[c0 + k];
        float cs = 0.f, cq2 = 0.f;
        #pragma unroll
        for (int i = 0; i < 4; i++) {
            float yv = acc[i][k] + b;
            g_y[(size_t)(c0 + k) * NPOS + nbase + n0 + i] = yv;
            cs += yv; cq2 += yv * yv;
        }
        atomicAdd(&ssum[c0 + k], cs);
        atomicAdd(&ssq[c0 + k], cq2);
    }
    __syncthreads();
    if (tid < CCH) {
        atomicAdd(&g_sum[tid], ssum[tid]);
        atomicAdd(&g_sq[tid],  ssq[tid]);
    }
}

// ---------------- kernel: BN (from global sums) + ReLU + residual ----------------
__global__ void k_final(const float* __restrict__ x,
                        const float* __restrict__ bnw, const float* __restrict__ bnb,
                        float* __restrict__ out) {
    const int c = blockIdx.y;
    const int n = blockIdx.x * 256 + threadIdx.x;
    if (n >= NPOS) return;
    const float inv = 1.f / (float)NPOS;
    float mean = g_sum[c] * inv;
    float var = g_sq[c] * inv - mean * mean;
    float rstd = rsqrtf(var + 1e-5f);
    size_t idx = (size_t)c * NPOS + n;
    float yv = g_y[idx];
    float o = (yv - mean) * rstd * bnw[c] + bnb[c];
    out[idx] = fmaxf(o, 0.f) + x[idx];
}

// ---------------- launch ----------------
extern "C" void kernel_launch(void* const* d_in, const int* in_sizes, int n_in,
                              void* d_out, int out_size) {
    const float* x   = (const float*)d_in[0];
    const float* wq  = (const float*)d_in[1];
    const float* bq  = (const float*)d_in[2];
    const float* wk  = (const float*)d_in[3];
    const float* bk  = (const float*)d_in[4];
    const float* wv  = (const float*)d_in[5];
    const float* bv  = (const float*)d_in[6];
    const float* wa  = (const float*)d_in[7];
    const float* ba  = (const float*)d_in[8];
    const float* bnw = (const float*)d_in[9];
    const float* bnb = (const float*)d_in[10];
    float* out = (float*)d_out;

    static int smem_set = 0;
    if (!smem_set) {
        cudaFuncSetAttribute(k_flash_mma, cudaFuncAttributeMaxDynamicSharedMemorySize,
                             FLASH_SMEM);
        smem_set = 1;
    }

    k_pre<<<814, 256>>>(x, wq, bq, wk, bk, wv, bv, wa);
    k_flash_mma<<<dim3(QT, NSPLIT), 256, FLASH_SMEM>>>();
    k_ygemm<<<NPOS / 32, 256>>>(ba);
    k_final<<<dim3(32, CCH), 256>>>(x, bnw, bnb, out);
}